// round 2
// baseline (speedup 1.0000x reference)
#include <cuda_runtime.h>
#include <cuda_bf16.h>
#include <math.h>

// Problem constants
#define BB 128
#define TT 2048
#define FF 80
#define NCLS 10
#define HH 32
#define MROWS (BB*TT)          // 262144
#define EPSBN 1e-5f

// ---------------- scratch (static __device__ arrays; no allocation) -------
__device__ float g_y1[(size_t)MROWS * 256];
__device__ float g_y2[(size_t)MROWS * 128];
__device__ float g_y3[(size_t)MROWS * 64];
__device__ float g_xpf[(size_t)MROWS * 96];
__device__ float g_xpb[(size_t)MROWS * 96];
__device__ float g_gru[(size_t)MROWS * 64];
__device__ float g_pooled[BB * 64];
__device__ float g_sums1[512];   // [sum(256) | sumsq(256)]
__device__ float g_sums2[256];
__device__ float g_sums3[128];
__device__ float g_sc1[256], g_sh1[256];
__device__ float g_sc2[128], g_sh2[128];
__device__ float g_sc3[64],  g_sh3[64];

// ---------------- zero the stat accumulators -------------------------------
__global__ void zero_stats_kernel(float* s1, float* s2, float* s3) {
    int i = threadIdx.x;
    if (i < 512) s1[i] = 0.f;
    if (i < 256) s2[i] = 0.f;
    if (i < 128) s3[i] = 0.f;
}

// =====================================================================
// SGEMM: C[M,N] = f(A[M,K]) @ W[N,K]^T + bias
//   f(a,k) = DO_T ? relu(a*scale[k]+shift[k]) : a
// BM=128, BN=64, BK=16, 128 threads, 8x8 micro-tile, double-buffered
// smem with transposed tiles (As[k][m], Ws[k][n]) for float4 LDS.
// If DO_STATS, per-column sum/sumsq accumulated into sums[] via atomics.
// Requires: K % 16 == 0, M % 128 == 0, row pitches 16B-aligned (all true).
// =====================================================================
template<int DO_T, int DO_STATS>
__global__ __launch_bounds__(128) void sgemm_kernel(
    const float* __restrict__ A, const float* __restrict__ W,
    const float* __restrict__ bias,
    const float* __restrict__ scale, const float* __restrict__ shift,
    float* __restrict__ C, float* __restrict__ sums,
    int M, int N, int K)
{
    __shared__ float As[2][16][132];   // [buf][k][m]  (132 = 128+4 pad, 16B-mult stride)
    __shared__ float Ws[2][16][68];    // [buf][k][n]  (68  = 64+4  pad)

    const int tid = threadIdx.x;
    const int tx = tid & 7;            // n-tile index 0..7
    const int ty = tid >> 3;           // m-tile index 0..15
    const int lane = tid & 31;
    const int bm0 = blockIdx.x * 128;
    const int bn0 = blockIdx.y * 64;

    const float* Arow = A + (size_t)(bm0 + tid) * K;
    const int wn = bn0 + tid;                    // W row for tid<64
    const float* Wrow = W + (size_t)wn * K;

    float acc[8][8];
#pragma unroll
    for (int i = 0; i < 8; i++)
#pragma unroll
        for (int j = 0; j < 8; j++) acc[i][j] = 0.f;

    const int nstage = K >> 4;

    float4 ar[4];
    float4 wr[4];

    // ---- load stage 0 into registers ----
#pragma unroll
    for (int q = 0; q < 4; q++) {
        float4 v = *(const float4*)(Arow + 4 * q);
        if (DO_T) {
            float4 sc = *(const float4*)(scale + 4 * q);
            float4 sh = *(const float4*)(shift + 4 * q);
            v.x = fmaxf(fmaf(v.x, sc.x, sh.x), 0.f);
            v.y = fmaxf(fmaf(v.y, sc.y, sh.y), 0.f);
            v.z = fmaxf(fmaf(v.z, sc.z, sh.z), 0.f);
            v.w = fmaxf(fmaf(v.w, sc.w, sh.w), 0.f);
        }
        ar[q] = v;
    }
    if (tid < 64) {
#pragma unroll
        for (int q = 0; q < 4; q++) {
            if (wn < N) wr[q] = *(const float4*)(Wrow + 4 * q);
            else        wr[q] = make_float4(0.f, 0.f, 0.f, 0.f);
        }
    }
    // write stage 0 to smem (transposed)
    {
        const float* arf = (const float*)ar;
#pragma unroll
        for (int k = 0; k < 16; k++) As[0][k][tid] = arf[k];
        if (tid < 64) {
            const float* wrf = (const float*)wr;
#pragma unroll
            for (int k = 0; k < 16; k++) Ws[0][k][tid] = wrf[k];
        }
    }
    __syncthreads();

    for (int s = 0; s < nstage; s++) {
        const int cur = s & 1;
        const int k0n = (s + 1) << 4;

        // prefetch next stage into registers
        if (s + 1 < nstage) {
#pragma unroll
            for (int q = 0; q < 4; q++) {
                float4 v = *(const float4*)(Arow + k0n + 4 * q);
                if (DO_T) {
                    float4 sc = *(const float4*)(scale + k0n + 4 * q);
                    float4 sh = *(const float4*)(shift + k0n + 4 * q);
                    v.x = fmaxf(fmaf(v.x, sc.x, sh.x), 0.f);
                    v.y = fmaxf(fmaf(v.y, sc.y, sh.y), 0.f);
                    v.z = fmaxf(fmaf(v.z, sc.z, sh.z), 0.f);
                    v.w = fmaxf(fmaf(v.w, sc.w, sh.w), 0.f);
                }
                ar[q] = v;
            }
            if (tid < 64) {
#pragma unroll
                for (int q = 0; q < 4; q++) {
                    if (wn < N) wr[q] = *(const float4*)(Wrow + k0n + 4 * q);
                    else        wr[q] = make_float4(0.f, 0.f, 0.f, 0.f);
                }
            }
        }

        // compute on current buffer
        const float* Asb = &As[cur][0][0];
        const float* Wsb = &Ws[cur][0][0];
#pragma unroll
        for (int k = 0; k < 16; k++) {
            float4 a0 = *(const float4*)(Asb + k * 132 + ty * 8);
            float4 a1 = *(const float4*)(Asb + k * 132 + ty * 8 + 4);
            float4 b0 = *(const float4*)(Wsb + k * 68 + tx * 8);
            float4 b1 = *(const float4*)(Wsb + k * 68 + tx * 8 + 4);
            float a[8] = {a0.x, a0.y, a0.z, a0.w, a1.x, a1.y, a1.z, a1.w};
            float b[8] = {b0.x, b0.y, b0.z, b0.w, b1.x, b1.y, b1.z, b1.w};
#pragma unroll
            for (int i = 0; i < 8; i++)
#pragma unroll
                for (int j = 0; j < 8; j++) acc[i][j] = fmaf(a[i], b[j], acc[i][j]);
        }

        // write next stage to the other buffer
        if (s + 1 < nstage) {
            const int nxt = cur ^ 1;
            const float* arf = (const float*)ar;
#pragma unroll
            for (int k = 0; k < 16; k++) As[nxt][k][tid] = arf[k];
            if (tid < 64) {
                const float* wrf = (const float*)wr;
#pragma unroll
                for (int k = 0; k < 16; k++) Ws[nxt][k][tid] = wrf[k];
            }
            __syncthreads();
        }
    }

    // ---- epilogue: bias add, store, fused column stats ----
    const int ncol0 = bn0 + tx * 8;
    float bv[8];
#pragma unroll
    for (int j = 0; j < 8; j++)
        bv[j] = (ncol0 + j < N) ? bias[ncol0 + j] : 0.f;

    float colsum[8], colsq[8];
#pragma unroll
    for (int j = 0; j < 8; j++) { colsum[j] = 0.f; colsq[j] = 0.f; }

#pragma unroll
    for (int i = 0; i < 8; i++) {
        const int row = bm0 + ty * 8 + i;
        float c[8];
#pragma unroll
        for (int j = 0; j < 8; j++) {
            c[j] = acc[i][j] + bv[j];
            if (DO_STATS) { colsum[j] += c[j]; colsq[j] += c[j] * c[j]; }
        }
        if (ncol0 < N) {
            float* Cp = C + (size_t)row * N + ncol0;
            *(float4*)(Cp)     = make_float4(c[0], c[1], c[2], c[3]);
            *(float4*)(Cp + 4) = make_float4(c[4], c[5], c[6], c[7]);
        }
    }

    if (DO_STATS) {
        // reduce across ty within warp (lanes with same tx = lane&7)
#pragma unroll
        for (int j = 0; j < 8; j++) {
            colsum[j] += __shfl_xor_sync(0xffffffffu, colsum[j], 8);
            colsum[j] += __shfl_xor_sync(0xffffffffu, colsum[j], 16);
            colsq[j]  += __shfl_xor_sync(0xffffffffu, colsq[j], 8);
            colsq[j]  += __shfl_xor_sync(0xffffffffu, colsq[j], 16);
        }
        if (lane < 8) {
#pragma unroll
            for (int j = 0; j < 8; j++) {
                int n = ncol0 + j;
                if (n < N) {
                    atomicAdd(&sums[n], colsum[j]);
                    atomicAdd(&sums[N + n], colsq[j]);
                }
            }
        }
    }
}

// ---------------- finalize BN affine ----------------------------------------
__global__ void finalize_bn_kernel(const float* __restrict__ sums,
                                   const float* __restrict__ gamma,
                                   const float* __restrict__ beta,
                                   float* __restrict__ scale,
                                   float* __restrict__ shift,
                                   int N, float invM)
{
    int c = blockIdx.x * blockDim.x + threadIdx.x;
    if (c < N) {
        float m = sums[c] * invM;
        float v = sums[N + c] * invM - m * m;
        float sc = gamma[c] * rsqrtf(v + EPSBN);
        scale[c] = sc;
        shift[c] = beta[c] - m * sc;
    }
}

// ---------------- GRU recurrence (one warp per (batch, direction)) ----------
__global__ __launch_bounds__(32) void gru_kernel(
    const float* __restrict__ xp_f, const float* __restrict__ xp_b,
    const float* __restrict__ Whh_f, const float* __restrict__ bhh_f,
    const float* __restrict__ Whh_b, const float* __restrict__ bhh_b,
    float* __restrict__ gru_out)
{
    int b = blockIdx.x;
    int dir = blockIdx.y;
    int j = threadIdx.x;   // 0..31

    const float* xp  = dir ? xp_b  : xp_f;
    const float* Whh = dir ? Whh_b : Whh_f;
    const float* bhh = dir ? bhh_b : bhh_f;

    float Wr[32], Wz[32], Wn[32];
#pragma unroll
    for (int k = 0; k < 32; k++) {
        Wr[k] = Whh[j * 32 + k];
        Wz[k] = Whh[(32 + j) * 32 + k];
        Wn[k] = Whh[(64 + j) * 32 + k];
    }
    float br = bhh[j], bz = bhh[32 + j], bnn = bhh[64 + j];

    float h = 0.f;
    size_t base = (size_t)b * TT * 96;
    int t = dir ? (TT - 1) : 0;
    int step = dir ? -1 : 1;

    // prefetch step 0
    float xr = xp[base + (size_t)t * 96 + j];
    float xz = xp[base + (size_t)t * 96 + 32 + j];
    float xn = xp[base + (size_t)t * 96 + 64 + j];

    for (int it = 0; it < TT; it++) {
        int tn = t + step;
        float nxr = 0.f, nxz = 0.f, nxn = 0.f;
        if (it + 1 < TT) {
            nxr = xp[base + (size_t)tn * 96 + j];
            nxz = xp[base + (size_t)tn * 96 + 32 + j];
            nxn = xp[base + (size_t)tn * 96 + 64 + j];
        }
        float accr = br, accz = bz, accn = bnn;
#pragma unroll
        for (int k = 0; k < 32; k++) {
            float hk = __shfl_sync(0xffffffffu, h, k);
            accr += Wr[k] * hk;
            accz += Wz[k] * hk;
            accn += Wn[k] * hk;
        }
        float r = 1.f / (1.f + __expf(-(xr + accr)));
        float z = 1.f / (1.f + __expf(-(xz + accz)));
        float n = tanhf(xn + r * accn);
        h = (1.f - z) * n + z * h;
        gru_out[((size_t)b * TT + t) * 64 + dir * 32 + j] = h;
        xr = nxr; xz = nxz; xn = nxn;
        t = tn;
    }
}

// ---------------- attention + softmax pooling (one block per batch) ---------
__global__ __launch_bounds__(256) void attn_kernel(
    const float* __restrict__ gru,
    const float* __restrict__ Wa1, const float* __restrict__ ba1,
    const float* __restrict__ Wa2, const float* __restrict__ ba2,
    float* __restrict__ pooled)
{
    __shared__ float s_scores[TT];
    __shared__ float s_Wa1[32 * 64];
    __shared__ float s_red[8];
    __shared__ float s_bcast[2];      // [0]=max, [1]=sumexp
    __shared__ float s_pool[4][64];

    int b = blockIdx.x;
    int tid = threadIdx.x;
    int lane = tid & 31;
    int w = tid >> 5;

    for (int i = tid; i < 32 * 64; i += 256) s_Wa1[i] = Wa1[i];
    __syncthreads();

    const float* gb = gru + (size_t)b * TT * 64;
    float wa2 = Wa2[lane];
    float ba2v = ba2[0];
    float ba1v = ba1[lane];

    for (int t = w; t < TT; t += 8) {
        const float* g = gb + (size_t)t * 64;
        float acc = ba1v;
#pragma unroll
        for (int k = 0; k < 64; k++) acc += s_Wa1[lane * 64 + k] * g[k];
        float v = tanhf(acc) * wa2;
#pragma unroll
        for (int o = 16; o; o >>= 1) v += __shfl_xor_sync(0xffffffffu, v, o);
        if (lane == 0) s_scores[t] = v + ba2v;
    }
    __syncthreads();

    // block max
    float m = -1e30f;
    for (int t = tid; t < TT; t += 256) m = fmaxf(m, s_scores[t]);
#pragma unroll
    for (int o = 16; o; o >>= 1) m = fmaxf(m, __shfl_xor_sync(0xffffffffu, m, o));
    if (lane == 0) s_red[w] = m;
    __syncthreads();
    if (tid == 0) {
        float mm = s_red[0];
#pragma unroll
        for (int i = 1; i < 8; i++) mm = fmaxf(mm, s_red[i]);
        s_bcast[0] = mm;
    }
    __syncthreads();
    m = s_bcast[0];

    // exp + sum
    float sum = 0.f;
    for (int t = tid; t < TT; t += 256) {
        float e = __expf(s_scores[t] - m);
        s_scores[t] = e;
        sum += e;
    }
#pragma unroll
    for (int o = 16; o; o >>= 1) sum += __shfl_xor_sync(0xffffffffu, sum, o);
    if (lane == 0) s_red[w] = sum;
    __syncthreads();
    if (tid == 0) {
        float ss = 0.f;
#pragma unroll
        for (int i = 0; i < 8; i++) ss += s_red[i];
        s_bcast[1] = ss;
    }
    __syncthreads();
    float sumexp = s_bcast[1];

    // weighted pool
    int c = tid & 63;
    int grp = tid >> 6;    // 0..3
    float acc = 0.f;
    for (int t = grp; t < TT; t += 4) acc += s_scores[t] * gb[(size_t)t * 64 + c];
    s_pool[grp][c] = acc;
    __syncthreads();
    if (tid < 64) {
        float tot = s_pool[0][tid] + s_pool[1][tid] + s_pool[2][tid] + s_pool[3][tid];
        pooled[b * 64 + tid] = tot / sumexp;
    }
}

// ---------------- classifier (single block, 128 threads = rows) -------------
__global__ __launch_bounds__(128) void cls_kernel(
    const float* __restrict__ pooled,
    const float* __restrict__ Wc1, const float* __restrict__ bc1,
    const float* __restrict__ gc, const float* __restrict__ bec,
    const float* __restrict__ Wc2, const float* __restrict__ bc2,
    float* __restrict__ out)
{
    __shared__ float s_sum[32], s_sq[32], s_scale[32], s_shift[32];
    int r = threadIdx.x;   // 0..127
    if (r < 32) { s_sum[r] = 0.f; s_sq[r] = 0.f; }
    __syncthreads();

    float x[64];
#pragma unroll
    for (int k = 0; k < 64; k++) x[k] = pooled[r * 64 + k];

    float q[32];
#pragma unroll
    for (int u = 0; u < 32; u++) {
        float a = bc1[u];
#pragma unroll
        for (int k = 0; k < 64; k++) a += Wc1[u * 64 + k] * x[k];
        q[u] = a;
        atomicAdd(&s_sum[u], a);
        atomicAdd(&s_sq[u], a * a);
    }
    __syncthreads();
    if (r < 32) {
        float m = s_sum[r] * (1.f / 128.f);
        float v = s_sq[r] * (1.f / 128.f) - m * m;
        float sc = gc[r] * rsqrtf(v + EPSBN);
        s_scale[r] = sc;
        s_shift[r] = bec[r] - m * sc;
    }
    __syncthreads();

    float qn[32];
#pragma unroll
    for (int u = 0; u < 32; u++) {
        float t = q[u] * s_scale[u] + s_shift[u];
        qn[u] = t > 0.f ? t : 0.f;
    }
#pragma unroll
    for (int c = 0; c < NCLS; c++) {
        float a = bc2[c];
#pragma unroll
        for (int k = 0; k < 32; k++) a += Wc2[c * 32 + k] * qn[k];
        out[r * NCLS + c] = a;
    }
}

// ---------------- launch ----------------------------------------------------
extern "C" void kernel_launch(void* const* d_in, const int* in_sizes, int n_in,
                              void* d_out, int out_size)
{
    (void)in_sizes; (void)n_in; (void)out_size;

    const float* x     = (const float*)d_in[0];
    const float* W1    = (const float*)d_in[1];
    const float* b1    = (const float*)d_in[2];
    const float* g1    = (const float*)d_in[3];
    const float* be1   = (const float*)d_in[4];
    const float* W2    = (const float*)d_in[5];
    const float* b2    = (const float*)d_in[6];
    const float* g2    = (const float*)d_in[7];
    const float* be2   = (const float*)d_in[8];
    const float* W3    = (const float*)d_in[9];
    const float* b3    = (const float*)d_in[10];
    const float* g3    = (const float*)d_in[11];
    const float* be3   = (const float*)d_in[12];
    const float* Wih_f = (const float*)d_in[13];
    const float* Whh_f = (const float*)d_in[14];
    const float* bih_f = (const float*)d_in[15];
    const float* bhh_f = (const float*)d_in[16];
    const float* Wih_b = (const float*)d_in[17];
    const float* Whh_b = (const float*)d_in[18];
    const float* bih_b = (const float*)d_in[19];
    const float* bhh_b = (const float*)d_in[20];
    const float* Wa1   = (const float*)d_in[21];
    const float* ba1   = (const float*)d_in[22];
    const float* Wa2   = (const float*)d_in[23];
    const float* ba2   = (const float*)d_in[24];
    const float* Wc1   = (const float*)d_in[25];
    const float* bc1   = (const float*)d_in[26];
    const float* gc    = (const float*)d_in[27];
    const float* bec   = (const float*)d_in[28];
    const float* Wc2   = (const float*)d_in[29];
    const float* bc2   = (const float*)d_in[30];
    float* out = (float*)d_out;

    // resolve scratch symbols (immediate API, capture-safe)
    float *y1, *y2, *y3, *xpf, *xpb, *gru, *pooled;
    float *sums1, *sums2, *sums3, *sc1, *sh1, *sc2, *sh2, *sc3, *sh3;
    cudaGetSymbolAddress((void**)&y1, g_y1);
    cudaGetSymbolAddress((void**)&y2, g_y2);
    cudaGetSymbolAddress((void**)&y3, g_y3);
    cudaGetSymbolAddress((void**)&xpf, g_xpf);
    cudaGetSymbolAddress((void**)&xpb, g_xpb);
    cudaGetSymbolAddress((void**)&gru, g_gru);
    cudaGetSymbolAddress((void**)&pooled, g_pooled);
    cudaGetSymbolAddress((void**)&sums1, g_sums1);
    cudaGetSymbolAddress((void**)&sums2, g_sums2);
    cudaGetSymbolAddress((void**)&sums3, g_sums3);
    cudaGetSymbolAddress((void**)&sc1, g_sc1);
    cudaGetSymbolAddress((void**)&sh1, g_sh1);
    cudaGetSymbolAddress((void**)&sc2, g_sc2);
    cudaGetSymbolAddress((void**)&sh2, g_sh2);
    cudaGetSymbolAddress((void**)&sc3, g_sc3);
    cudaGetSymbolAddress((void**)&sh3, g_sh3);

    const float invM = 1.f / (float)MROWS;
    const int gx = MROWS / 128;

    zero_stats_kernel<<<1, 512>>>(sums1, sums2, sums3);

    // L1: y1 = x @ W1^T + b1     (N=256, K=80) + fused column stats
    sgemm_kernel<0,1><<<dim3(gx, 4), 128>>>(x, W1, b1, nullptr, nullptr,
                                            y1, sums1, MROWS, 256, FF);
    finalize_bn_kernel<<<1, 256>>>(sums1, g1, be1, sc1, sh1, 256, invM);

    // L2: y2 = relu(bn1(y1)) @ W2^T + b2   (N=128, K=256)
    sgemm_kernel<1,1><<<dim3(gx, 2), 128>>>(y1, W2, b2, sc1, sh1,
                                            y2, sums2, MROWS, 128, 256);
    finalize_bn_kernel<<<1, 128>>>(sums2, g2, be2, sc2, sh2, 128, invM);

    // L3: y3 = relu(bn2(y2)) @ W3^T + b3   (N=64, K=128)
    sgemm_kernel<1,1><<<dim3(gx, 1), 128>>>(y2, W3, b3, sc2, sh2,
                                            y3, sums3, MROWS, 64, 128);
    finalize_bn_kernel<<<1, 64>>>(sums3, g3, be3, sc3, sh3, 64, invM);

    // GRU input projections: xp = relu(bn3(y3)) @ Wih^T + bih   (N=96, K=64)
    sgemm_kernel<1,0><<<dim3(gx, 2), 128>>>(y3, Wih_f, bih_f, sc3, sh3,
                                            xpf, nullptr, MROWS, 96, 64);
    sgemm_kernel<1,0><<<dim3(gx, 2), 128>>>(y3, Wih_b, bih_b, sc3, sh3,
                                            xpb, nullptr, MROWS, 96, 64);

    // GRU recurrence (both directions)
    gru_kernel<<<dim3(BB, 2), 32>>>(xpf, xpb, Whh_f, bhh_f, Whh_b, bhh_b, gru);

    // attention pooling
    attn_kernel<<<BB, 256>>>(gru, Wa1, ba1, Wa2, ba2, pooled);

    // classifier
    cls_kernel<<<1, 128>>>(pooled, Wc1, bc1, gc, bec, Wc2, bc2, out);
}

// round 3
// speedup vs baseline: 1.8737x; 1.8737x over previous
#include <cuda_runtime.h>
#include <cuda_bf16.h>
#include <math.h>

// Problem constants
#define BB 128
#define TT 2048
#define FF 80
#define NCLS 10
#define HH 32
#define MROWS (BB*TT)          // 262144
#define EPSBN 1e-5f

// ---------------- scratch (static __device__ arrays; no allocation) -------
__device__ float g_y1[(size_t)MROWS * 256];
__device__ float g_y2[(size_t)MROWS * 128];
__device__ float g_y3[(size_t)MROWS * 64];
__device__ float g_xpf[(size_t)MROWS * 96];
__device__ float g_xpb[(size_t)MROWS * 96];
__device__ float g_gru[(size_t)MROWS * 64];
__device__ float g_pooled[BB * 64];
__device__ float g_sums1[512];   // [sum(256) | sumsq(256)]
__device__ float g_sums2[256];
__device__ float g_sums3[128];
__device__ float g_sc1[256], g_sh1[256];
__device__ float g_sc2[128], g_sh2[128];
__device__ float g_sc3[64],  g_sh3[64];

// ---------------- zero the stat accumulators -------------------------------
__global__ void zero_stats_kernel(float* s1, float* s2, float* s3) {
    int i = threadIdx.x;
    if (i < 512) s1[i] = 0.f;
    if (i < 256) s2[i] = 0.f;
    if (i < 128) s3[i] = 0.f;
}

// =====================================================================
// SGEMM: C[M,N] = f(A[M,K]) @ W[N,K]^T + bias
//   f(a,k) = DO_T ? relu(a*scale[k]+shift[k]) : a
// BM=128, BN=128, BK=16, 256 threads, 8x8 micro-tile.
// Global loads coalesced (4 threads per row, float4 => nL=8 lines/LDG).
// Transposed smem tiles (As[k][m], Bs[k][n]) for float4 LDS, double-buffered.
// DO_STATS: per-column sum/sumsq via smem reduction + 1 atomic/col/block.
// Requires: K%16==0, M%128==0, N%8==0.
// =====================================================================
template<int DO_T, int DO_STATS>
__global__ __launch_bounds__(256, 2) void sgemm_kernel(
    const float* __restrict__ A, const float* __restrict__ W,
    const float* __restrict__ bias,
    const float* __restrict__ scale, const float* __restrict__ shift,
    float* __restrict__ C, float* __restrict__ sums,
    int M, int N, int K)
{
    __shared__ float As[2][16][132];   // [buf][k][m], 132 = 128+4 (16B-mult stride)
    __shared__ float Bs[2][16][132];
    __shared__ float s_sum[128], s_sq[128];

    const int tid = threadIdx.x;
    const int tx = tid & 15;           // n-tile 0..15
    const int ty = tid >> 4;           // m-tile 0..15
    const int lane = tid & 31;
    const int bm0 = blockIdx.x * 128;
    const int bn0 = blockIdx.y * 128;

    if (DO_STATS && tid < 128) { s_sum[tid] = 0.f; s_sq[tid] = 0.f; }

    // load mapping: 4 threads per row, 2 row-passes
    const int lr = tid >> 2;           // 0..63
    const int kq = (tid & 3) * 4;      // 0,4,8,12
    const int ar0i = bm0 + lr;
    const int ar1i = bm0 + lr + 64;
    const int wr0i = bn0 + lr;
    const int wr1i = bn0 + lr + 64;
    const float* A0 = A + (size_t)ar0i * K + kq;
    const float* A1 = A + (size_t)ar1i * K + kq;
    const float* W0 = W + (size_t)wr0i * K + kq;
    const float* W1 = W + (size_t)wr1i * K + kq;
    const bool w0ok = (wr0i < N);
    const bool w1ok = (wr1i < N);

    float acc[8][8];
#pragma unroll
    for (int i = 0; i < 8; i++)
#pragma unroll
        for (int j = 0; j < 8; j++) acc[i][j] = 0.f;

    const int nstage = K >> 4;

    float4 a0r, a1r, w0r, w1r;

    // ---- stage 0 loads ----
    {
        float4 v0 = *(const float4*)(A0);
        float4 v1 = *(const float4*)(A1);
        if (DO_T) {
            float4 sc = *(const float4*)(scale + kq);
            float4 sh = *(const float4*)(shift + kq);
            v0.x = fmaxf(fmaf(v0.x, sc.x, sh.x), 0.f);
            v0.y = fmaxf(fmaf(v0.y, sc.y, sh.y), 0.f);
            v0.z = fmaxf(fmaf(v0.z, sc.z, sh.z), 0.f);
            v0.w = fmaxf(fmaf(v0.w, sc.w, sh.w), 0.f);
            v1.x = fmaxf(fmaf(v1.x, sc.x, sh.x), 0.f);
            v1.y = fmaxf(fmaf(v1.y, sc.y, sh.y), 0.f);
            v1.z = fmaxf(fmaf(v1.z, sc.z, sh.z), 0.f);
            v1.w = fmaxf(fmaf(v1.w, sc.w, sh.w), 0.f);
        }
        a0r = v0; a1r = v1;
        w0r = w0ok ? *(const float4*)(W0) : make_float4(0.f,0.f,0.f,0.f);
        w1r = w1ok ? *(const float4*)(W1) : make_float4(0.f,0.f,0.f,0.f);
    }
    // write stage 0 (transposed)
    {
        const float* a0f = (const float*)&a0r;
        const float* a1f = (const float*)&a1r;
        const float* w0f = (const float*)&w0r;
        const float* w1f = (const float*)&w1r;
#pragma unroll
        for (int i = 0; i < 4; i++) {
            As[0][kq + i][lr]      = a0f[i];
            As[0][kq + i][lr + 64] = a1f[i];
            Bs[0][kq + i][lr]      = w0f[i];
            Bs[0][kq + i][lr + 64] = w1f[i];
        }
    }
    __syncthreads();

    for (int s = 0; s < nstage; s++) {
        const int cur = s & 1;
        const int k0n = (s + 1) << 4;

        // prefetch next stage into registers
        if (s + 1 < nstage) {
            float4 v0 = *(const float4*)(A0 + k0n);
            float4 v1 = *(const float4*)(A1 + k0n);
            if (DO_T) {
                float4 sc = *(const float4*)(scale + k0n + kq);
                float4 sh = *(const float4*)(shift + k0n + kq);
                v0.x = fmaxf(fmaf(v0.x, sc.x, sh.x), 0.f);
                v0.y = fmaxf(fmaf(v0.y, sc.y, sh.y), 0.f);
                v0.z = fmaxf(fmaf(v0.z, sc.z, sh.z), 0.f);
                v0.w = fmaxf(fmaf(v0.w, sc.w, sh.w), 0.f);
                v1.x = fmaxf(fmaf(v1.x, sc.x, sh.x), 0.f);
                v1.y = fmaxf(fmaf(v1.y, sc.y, sh.y), 0.f);
                v1.z = fmaxf(fmaf(v1.z, sc.z, sh.z), 0.f);
                v1.w = fmaxf(fmaf(v1.w, sc.w, sh.w), 0.f);
            }
            a0r = v0; a1r = v1;
            w0r = w0ok ? *(const float4*)(W0 + k0n) : make_float4(0.f,0.f,0.f,0.f);
            w1r = w1ok ? *(const float4*)(W1 + k0n) : make_float4(0.f,0.f,0.f,0.f);
        }

        // compute on current buffer
#pragma unroll
        for (int k = 0; k < 16; k++) {
            float4 av0 = *(const float4*)(&As[cur][k][ty * 8]);
            float4 av1 = *(const float4*)(&As[cur][k][ty * 8 + 4]);
            float4 bv0 = *(const float4*)(&Bs[cur][k][tx * 8]);
            float4 bv1 = *(const float4*)(&Bs[cur][k][tx * 8 + 4]);
            float a[8] = {av0.x, av0.y, av0.z, av0.w, av1.x, av1.y, av1.z, av1.w};
            float b[8] = {bv0.x, bv0.y, bv0.z, bv0.w, bv1.x, bv1.y, bv1.z, bv1.w};
#pragma unroll
            for (int i = 0; i < 8; i++)
#pragma unroll
                for (int j = 0; j < 8; j++) acc[i][j] = fmaf(a[i], b[j], acc[i][j]);
        }

        if (s + 1 < nstage) {
            const int nxt = cur ^ 1;
            const float* a0f = (const float*)&a0r;
            const float* a1f = (const float*)&a1r;
            const float* w0f = (const float*)&w0r;
            const float* w1f = (const float*)&w1r;
            __syncthreads();
#pragma unroll
            for (int i = 0; i < 4; i++) {
                As[nxt][kq + i][lr]      = a0f[i];
                As[nxt][kq + i][lr + 64] = a1f[i];
                Bs[nxt][kq + i][lr]      = w0f[i];
                Bs[nxt][kq + i][lr + 64] = w1f[i];
            }
            __syncthreads();
        }
    }

    // ---- epilogue ----
    const int ncol0 = bn0 + tx * 8;
    float bv[8];
#pragma unroll
    for (int j = 0; j < 8; j++)
        bv[j] = (ncol0 < N) ? bias[ncol0 + j] : 0.f;

    float colsum[8], colsq[8];
#pragma unroll
    for (int j = 0; j < 8; j++) { colsum[j] = 0.f; colsq[j] = 0.f; }

#pragma unroll
    for (int i = 0; i < 8; i++) {
        const int row = bm0 + ty * 8 + i;
        float c[8];
#pragma unroll
        for (int j = 0; j < 8; j++) {
            c[j] = acc[i][j] + bv[j];
            if (DO_STATS) { colsum[j] += c[j]; colsq[j] += c[j] * c[j]; }
        }
        if (ncol0 < N) {
            float* Cp = C + (size_t)row * N + ncol0;
            *(float4*)(Cp)     = make_float4(c[0], c[1], c[2], c[3]);
            *(float4*)(Cp + 4) = make_float4(c[4], c[5], c[6], c[7]);
        }
    }

    if (DO_STATS) {
        // combine the two ty's within each warp (lanes l and l^16 share tx)
#pragma unroll
        for (int j = 0; j < 8; j++) {
            colsum[j] += __shfl_xor_sync(0xffffffffu, colsum[j], 16);
            colsq[j]  += __shfl_xor_sync(0xffffffffu, colsq[j], 16);
        }
        __syncthreads();   // s_sum/s_sq init + smem tiles done
        if (lane < 16) {
#pragma unroll
            for (int j = 0; j < 8; j++) {
                atomicAdd(&s_sum[tx * 8 + j], colsum[j]);
                atomicAdd(&s_sq[tx * 8 + j],  colsq[j]);
            }
        }
        __syncthreads();
        if (tid < 128) {
            int n = bn0 + tid;
            if (n < N) {
                atomicAdd(&sums[n],     s_sum[tid]);
                atomicAdd(&sums[N + n], s_sq[tid]);
            }
        }
    }
}

// ---------------- finalize BN affine ----------------------------------------
__global__ void finalize_bn_kernel(const float* __restrict__ sums,
                                   const float* __restrict__ gamma,
                                   const float* __restrict__ beta,
                                   float* __restrict__ scale,
                                   float* __restrict__ shift,
                                   int N, float invM)
{
    int c = blockIdx.x * blockDim.x + threadIdx.x;
    if (c < N) {
        float m = sums[c] * invM;
        float v = sums[N + c] * invM - m * m;
        float sc = gamma[c] * rsqrtf(v + EPSBN);
        scale[c] = sc;
        shift[c] = beta[c] - m * sc;
    }
}

// ---------------- GRU recurrence (one warp per (batch, direction)) ----------
// depth-4 software-pipelined xp prefetch + 4-way split accumulators
__global__ __launch_bounds__(32) void gru_kernel(
    const float* __restrict__ xp_f, const float* __restrict__ xp_b,
    const float* __restrict__ Whh_f, const float* __restrict__ bhh_f,
    const float* __restrict__ Whh_b, const float* __restrict__ bhh_b,
    float* __restrict__ gru_out)
{
    int b = blockIdx.x;
    int dir = blockIdx.y;
    int j = threadIdx.x;   // 0..31

    const float* xp  = dir ? xp_b  : xp_f;
    const float* Whh = dir ? Whh_b : Whh_f;
    const float* bhh = dir ? bhh_b : bhh_f;

    float Wr[32], Wz[32], Wn[32];
#pragma unroll
    for (int k = 0; k < 32; k++) {
        Wr[k] = Whh[j * 32 + k];
        Wz[k] = Whh[(32 + j) * 32 + k];
        Wn[k] = Whh[(64 + j) * 32 + k];
    }
    float br = bhh[j], bz = bhh[32 + j], bnn = bhh[64 + j];

    float h = 0.f;
    const int st = dir ? -96 : 96;            // element stride per step
    int tcur = dir ? (TT - 1) : 0;
    const float* cur = xp + (size_t)b * TT * 96 + (size_t)tcur * 96;
    const float* pf = cur + 4 * st;           // prefetch pointer (4 ahead)
    float* outp = gru_out + ((size_t)b * TT + tcur) * 64 + dir * 32 + j;
    const long ost = dir ? -64 : 64;

    float fr[4], fz[4], fn[4];
#pragma unroll
    for (int q = 0; q < 4; q++) {
        const float* p = cur + q * st;
        fr[q] = p[j]; fz[q] = p[32 + j]; fn[q] = p[64 + j];
    }

    for (int it = 0; it < TT; it += 4) {
        float nfr[4], nfz[4], nfn[4];
        const bool more = (it + 4 < TT);
        if (more) {
#pragma unroll
            for (int q = 0; q < 4; q++) {
                const float* p = pf + q * st;
                nfr[q] = p[j]; nfz[q] = p[32 + j]; nfn[q] = p[64 + j];
            }
        }
        pf += 4 * st;

#pragma unroll
        for (int u = 0; u < 4; u++) {
            float ar0 = 0.f, ar1 = 0.f, ar2 = 0.f, ar3 = 0.f;
            float az0 = 0.f, az1 = 0.f, az2 = 0.f, az3 = 0.f;
            float an0 = 0.f, an1 = 0.f, an2 = 0.f, an3 = 0.f;
#pragma unroll
            for (int k = 0; k < 8; k++) {
                float h0 = __shfl_sync(0xffffffffu, h, k);
                float h1 = __shfl_sync(0xffffffffu, h, k + 8);
                float h2 = __shfl_sync(0xffffffffu, h, k + 16);
                float h3 = __shfl_sync(0xffffffffu, h, k + 24);
                ar0 = fmaf(Wr[k], h0, ar0);
                ar1 = fmaf(Wr[k + 8], h1, ar1);
                ar2 = fmaf(Wr[k + 16], h2, ar2);
                ar3 = fmaf(Wr[k + 24], h3, ar3);
                az0 = fmaf(Wz[k], h0, az0);
                az1 = fmaf(Wz[k + 8], h1, az1);
                az2 = fmaf(Wz[k + 16], h2, az2);
                az3 = fmaf(Wz[k + 24], h3, az3);
                an0 = fmaf(Wn[k], h0, an0);
                an1 = fmaf(Wn[k + 8], h1, an1);
                an2 = fmaf(Wn[k + 16], h2, an2);
                an3 = fmaf(Wn[k + 24], h3, an3);
            }
            float accr = br + (ar0 + ar1) + (ar2 + ar3);
            float accz = bz + (az0 + az1) + (az2 + az3);
            float accn = bnn + (an0 + an1) + (an2 + an3);
            float r = 1.f / (1.f + __expf(-(fr[u] + accr)));
            float z = 1.f / (1.f + __expf(-(fz[u] + accz)));
            float pre = fn[u] + r * accn;
            // tanh(x) = 1 - 2/(exp(2x)+1)
            float n = 1.f - 2.f / (__expf(2.f * pre) + 1.f);
            h = (1.f - z) * n + z * h;
            *outp = h;
            outp += ost;
        }
#pragma unroll
        for (int q = 0; q < 4; q++) { fr[q] = nfr[q]; fz[q] = nfz[q]; fn[q] = nfn[q]; }
    }
}

// ---------------- attention + softmax pooling (one block per batch) ---------
__global__ __launch_bounds__(256) void attn_kernel(
    const float* __restrict__ gru,
    const float* __restrict__ Wa1, const float* __restrict__ ba1,
    const float* __restrict__ Wa2, const float* __restrict__ ba2,
    float* __restrict__ pooled)
{
    __shared__ float s_scores[TT];
    __shared__ float s_Wa1[32 * 64];
    __shared__ float s_red[8];
    __shared__ float s_bcast[2];
    __shared__ float s_pool[4][64];

    int b = blockIdx.x;
    int tid = threadIdx.x;
    int lane = tid & 31;
    int w = tid >> 5;

    for (int i = tid; i < 32 * 64; i += 256) s_Wa1[i] = Wa1[i];
    __syncthreads();

    const float* gb = gru + (size_t)b * TT * 64;
    float wa2 = Wa2[lane];
    float ba2v = ba2[0];
    float ba1v = ba1[lane];

    for (int t = w; t < TT; t += 8) {
        const float* g = gb + (size_t)t * 64;
        float acc = ba1v;
#pragma unroll
        for (int k = 0; k < 64; k++) acc += s_Wa1[lane * 64 + k] * g[k];
        float v = tanhf(acc) * wa2;
#pragma unroll
        for (int o = 16; o; o >>= 1) v += __shfl_xor_sync(0xffffffffu, v, o);
        if (lane == 0) s_scores[t] = v + ba2v;
    }
    __syncthreads();

    float m = -1e30f;
    for (int t = tid; t < TT; t += 256) m = fmaxf(m, s_scores[t]);
#pragma unroll
    for (int o = 16; o; o >>= 1) m = fmaxf(m, __shfl_xor_sync(0xffffffffu, m, o));
    if (lane == 0) s_red[w] = m;
    __syncthreads();
    if (tid == 0) {
        float mm = s_red[0];
#pragma unroll
        for (int i = 1; i < 8; i++) mm = fmaxf(mm, s_red[i]);
        s_bcast[0] = mm;
    }
    __syncthreads();
    m = s_bcast[0];

    float sum = 0.f;
    for (int t = tid; t < TT; t += 256) {
        float e = __expf(s_scores[t] - m);
        s_scores[t] = e;
        sum += e;
    }
#pragma unroll
    for (int o = 16; o; o >>= 1) sum += __shfl_xor_sync(0xffffffffu, sum, o);
    if (lane == 0) s_red[w] = sum;
    __syncthreads();
    if (tid == 0) {
        float ss = 0.f;
#pragma unroll
        for (int i = 0; i < 8; i++) ss += s_red[i];
        s_bcast[1] = ss;
    }
    __syncthreads();
    float sumexp = s_bcast[1];

    int c = tid & 63;
    int grp = tid >> 6;
    float acc = 0.f;
    for (int t = grp; t < TT; t += 4) acc += s_scores[t] * gb[(size_t)t * 64 + c];
    s_pool[grp][c] = acc;
    __syncthreads();
    if (tid < 64) {
        float tot = s_pool[0][tid] + s_pool[1][tid] + s_pool[2][tid] + s_pool[3][tid];
        pooled[b * 64 + tid] = tot / sumexp;
    }
}

// ---------------- classifier (single block, 128 threads = rows) -------------
__global__ __launch_bounds__(128) void cls_kernel(
    const float* __restrict__ pooled,
    const float* __restrict__ Wc1, const float* __restrict__ bc1,
    const float* __restrict__ gc, const float* __restrict__ bec,
    const float* __restrict__ Wc2, const float* __restrict__ bc2,
    float* __restrict__ out)
{
    __shared__ float s_sum[32], s_sq[32], s_scale[32], s_shift[32];
    int r = threadIdx.x;
    if (r < 32) { s_sum[r] = 0.f; s_sq[r] = 0.f; }
    __syncthreads();

    float x[64];
#pragma unroll
    for (int k = 0; k < 64; k++) x[k] = pooled[r * 64 + k];

    float q[32];
#pragma unroll
    for (int u = 0; u < 32; u++) {
        float a = bc1[u];
#pragma unroll
        for (int k = 0; k < 64; k++) a += Wc1[u * 64 + k] * x[k];
        q[u] = a;
        atomicAdd(&s_sum[u], a);
        atomicAdd(&s_sq[u], a * a);
    }
    __syncthreads();
    if (r < 32) {
        float m = s_sum[r] * (1.f / 128.f);
        float v = s_sq[r] * (1.f / 128.f) - m * m;
        float sc = gc[r] * rsqrtf(v + EPSBN);
        s_scale[r] = sc;
        s_shift[r] = bec[r] - m * sc;
    }
    __syncthreads();

    float qn[32];
#pragma unroll
    for (int u = 0; u < 32; u++) {
        float t = q[u] * s_scale[u] + s_shift[u];
        qn[u] = t > 0.f ? t : 0.f;
    }
#pragma unroll
    for (int c = 0; c < NCLS; c++) {
        float a = bc2[c];
#pragma unroll
        for (int k = 0; k < 32; k++) a += Wc2[c * 32 + k] * qn[k];
        out[r * NCLS + c] = a;
    }
}

// ---------------- launch ----------------------------------------------------
extern "C" void kernel_launch(void* const* d_in, const int* in_sizes, int n_in,
                              void* d_out, int out_size)
{
    (void)in_sizes; (void)n_in; (void)out_size;

    const float* x     = (const float*)d_in[0];
    const float* W1    = (const float*)d_in[1];
    const float* b1    = (const float*)d_in[2];
    const float* g1    = (const float*)d_in[3];
    const float* be1   = (const float*)d_in[4];
    const float* W2    = (const float*)d_in[5];
    const float* b2    = (const float*)d_in[6];
    const float* g2    = (const float*)d_in[7];
    const float* be2   = (const float*)d_in[8];
    const float* W3    = (const float*)d_in[9];
    const float* b3    = (const float*)d_in[10];
    const float* g3    = (const float*)d_in[11];
    const float* be3   = (const float*)d_in[12];
    const float* Wih_f = (const float*)d_in[13];
    const float* Whh_f = (const float*)d_in[14];
    const float* bih_f = (const float*)d_in[15];
    const float* bhh_f = (const float*)d_in[16];
    const float* Wih_b = (const float*)d_in[17];
    const float* Whh_b = (const float*)d_in[18];
    const float* bih_b = (const float*)d_in[19];
    const float* bhh_b = (const float*)d_in[20];
    const float* Wa1   = (const float*)d_in[21];
    const float* ba1   = (const float*)d_in[22];
    const float* Wa2   = (const float*)d_in[23];
    const float* ba2   = (const float*)d_in[24];
    const float* Wc1   = (const float*)d_in[25];
    const float* bc1   = (const float*)d_in[26];
    const float* gc    = (const float*)d_in[27];
    const float* bec   = (const float*)d_in[28];
    const float* Wc2   = (const float*)d_in[29];
    const float* bc2   = (const float*)d_in[30];
    float* out = (float*)d_out;

    float *y1, *y2, *y3, *xpf, *xpb, *gru, *pooled;
    float *sums1, *sums2, *sums3, *sc1, *sh1, *sc2, *sh2, *sc3, *sh3;
    cudaGetSymbolAddress((void**)&y1, g_y1);
    cudaGetSymbolAddress((void**)&y2, g_y2);
    cudaGetSymbolAddress((void**)&y3, g_y3);
    cudaGetSymbolAddress((void**)&xpf, g_xpf);
    cudaGetSymbolAddress((void**)&xpb, g_xpb);
    cudaGetSymbolAddress((void**)&gru, g_gru);
    cudaGetSymbolAddress((void**)&pooled, g_pooled);
    cudaGetSymbolAddress((void**)&sums1, g_sums1);
    cudaGetSymbolAddress((void**)&sums2, g_sums2);
    cudaGetSymbolAddress((void**)&sums3, g_sums3);
    cudaGetSymbolAddress((void**)&sc1, g_sc1);
    cudaGetSymbolAddress((void**)&sh1, g_sh1);
    cudaGetSymbolAddress((void**)&sc2, g_sc2);
    cudaGetSymbolAddress((void**)&sh2, g_sh2);
    cudaGetSymbolAddress((void**)&sc3, g_sc3);
    cudaGetSymbolAddress((void**)&sh3, g_sh3);

    const float invM = 1.f / (float)MROWS;
    const int gx = MROWS / 128;

    zero_stats_kernel<<<1, 512>>>(sums1, sums2, sums3);

    // L1: y1 = x @ W1^T + b1     (N=256, K=80) + fused column stats
    sgemm_kernel<0,1><<<dim3(gx, 2), 256>>>(x, W1, b1, nullptr, nullptr,
                                            y1, sums1, MROWS, 256, FF);
    finalize_bn_kernel<<<1, 256>>>(sums1, g1, be1, sc1, sh1, 256, invM);

    // L2: y2 = relu(bn1(y1)) @ W2^T + b2   (N=128, K=256)
    sgemm_kernel<1,1><<<dim3(gx, 1), 256>>>(y1, W2, b2, sc1, sh1,
                                            y2, sums2, MROWS, 128, 256);
    finalize_bn_kernel<<<1, 128>>>(sums2, g2, be2, sc2, sh2, 128, invM);

    // L3: y3 = relu(bn2(y2)) @ W3^T + b3   (N=64, K=128)
    sgemm_kernel<1,1><<<dim3(gx, 1), 256>>>(y2, W3, b3, sc2, sh2,
                                            y3, sums3, MROWS, 64, 128);
    finalize_bn_kernel<<<1, 64>>>(sums3, g3, be3, sc3, sh3, 64, invM);

    // GRU input projections: xp = relu(bn3(y3)) @ Wih^T + bih   (N=96, K=64)
    sgemm_kernel<1,0><<<dim3(gx, 1), 256>>>(y3, Wih_f, bih_f, sc3, sh3,
                                            xpf, nullptr, MROWS, 96, 64);
    sgemm_kernel<1,0><<<dim3(gx, 1), 256>>>(y3, Wih_b, bih_b, sc3, sh3,
                                            xpb, nullptr, MROWS, 96, 64);

    // GRU recurrence
    gru_kernel<<<dim3(BB, 2), 32>>>(xpf, xpb, Whh_f, bhh_f, Whh_b, bhh_b, gru);

    // attention pooling
    attn_kernel<<<BB, 256>>>(gru, Wa1, ba1, Wa2, ba2, pooled);

    // classifier
    cls_kernel<<<1, 128>>>(pooled, Wc1, bc1, gc, bec, Wc2, bc2, out);
}

// round 5
// speedup vs baseline: 2.3762x; 1.2681x over previous
#include <cuda_runtime.h>
#include <cuda_bf16.h>
#include <stdint.h>
#include <math.h>

// Problem constants
#define BB 128
#define TT 2048
#define FF 80
#define NCLS 10
#define HH 32
#define MROWS (BB*TT)          // 262144
#define EPSBN 1e-5f

// ---------------- scratch (static __device__ arrays; no allocation) -------
__device__ float g_y1[(size_t)MROWS * 256];
__device__ float g_y2[(size_t)MROWS * 128];
__device__ float g_y3[(size_t)MROWS * 64];
__device__ float g_xpf[(size_t)MROWS * 96];
__device__ float g_xpb[(size_t)MROWS * 96];
__device__ float g_gru[(size_t)MROWS * 64];
__device__ float g_pooled[BB * 64];
__device__ float g_sums1[512];
__device__ float g_sums2[256];
__device__ float g_sums3[128];
__device__ float g_sc1[256], g_sh1[256];
__device__ float g_sc2[128], g_sh2[128];
__device__ float g_sc3[64],  g_sh3[64];

__global__ void zero_stats_kernel(float* s1, float* s2, float* s3) {
    int i = threadIdx.x;
    if (i < 512) s1[i] = 0.f;
    if (i < 256) s2[i] = 0.f;
    if (i < 128) s3[i] = 0.f;
}

// ---------------- helpers ----------------------------------------------------
__device__ __forceinline__ uint32_t pack_bf2(float x, float y) {
    unsigned short h0 = __bfloat16_as_ushort(__float2bfloat16_rn(x));
    unsigned short h1 = __bfloat16_as_ushort(__float2bfloat16_rn(y));
    return (uint32_t)h0 | ((uint32_t)h1 << 16);
}

__device__ __forceinline__ void mma_bf16(float* c, const uint32_t* a, const uint32_t* b) {
    asm volatile(
        "mma.sync.aligned.m16n8k16.row.col.f32.bf16.bf16.f32 "
        "{%0,%1,%2,%3}, {%4,%5,%6,%7}, {%8,%9}, {%0,%1,%2,%3};"
        : "+f"(c[0]), "+f"(c[1]), "+f"(c[2]), "+f"(c[3])
        : "r"(a[0]), "r"(a[1]), "r"(a[2]), "r"(a[3]), "r"(b[0]), "r"(b[1]));
}

// =====================================================================
// BGEMM (tensor-core, bf16 hi/lo split): C[M,N] = f(A[M,K]) @ W[N,K]^T + bias
//   f(a,k) = DO_T ? relu(a*scale[k]+shift[k]) : a
// BM=128, BN=128, BK=16 (fp32 k), 256 threads (8 warps, 4x2 m/n split).
// Operands staged in mma-fragment order:
//   A frags: [m_tile(8)][lane(32)][reg(4)] u32 (bf16x2), hi and lo arrays
//   B frags: [n_tile(16)][lane(32)][reg(2)] u32, hi and lo arrays
// C = Ah*Wh + Ah*Wl + Al*Wh (error ~2^-16, effectively fp32).
// DO_STATS: fused per-column sum/sumsq.
// Requires: K%16==0, M%128==0, N even.
// =====================================================================
template<int DO_T, int DO_STATS>
__global__ __launch_bounds__(256, 2) void bgemm_kernel(
    const float* __restrict__ A, const float* __restrict__ W,
    const float* __restrict__ bias,
    const float* __restrict__ scale, const float* __restrict__ shift,
    float* __restrict__ C, float* __restrict__ sums,
    int M, int N, int K)
{
    __shared__ __align__(16) uint32_t sAh[2][8][32][4];
    __shared__ __align__(16) uint32_t sAl[2][8][32][4];
    __shared__ __align__(16) uint32_t sBh[2][16][32][2];
    __shared__ __align__(16) uint32_t sBl[2][16][32][2];
    __shared__ float s_sum[128], s_sq[128];

    const int tid = threadIdx.x;
    const int lane = tid & 31;
    const int wid = tid >> 5;
    const int wm = wid & 3;         // warp m-group (32 rows each)
    const int wn = wid >> 2;        // warp n-group (64 cols each)
    const int bm0 = blockIdx.x * 128;
    const int bn0 = blockIdx.y * 128;

    if (DO_STATS && tid < 128) { s_sum[tid] = 0.f; s_sq[tid] = 0.f; }

    // ---- per-thread staging mappings (4 passes, 4 fp32-pairs each) ----
    const float2* aptr[4];
    const float2* wptr[4];
    int aoff[4], woff[4];
    bool wok[4];
    int kpv[4];
#pragma unroll
    for (int i = 0; i < 4; i++) {
        int p = tid + i * 256;          // pair index 0..1023
        int m = p >> 3;                  // 0..127
        int kp = p & 7;                  // k-pair 0..7 (k = 2kp, 2kp+1)
        kpv[i] = kp;
        aptr[i] = (const float2*)(A + (size_t)(bm0 + m) * K) + kp;
        int mt = m >> 4, r = m & 15;
        aoff[i] = ((mt * 32) + (r & 7) * 4 + (kp & 3)) * 4 + ((r >> 3) + 2 * (kp >> 2));
        int n = bn0 + m;
        wok[i] = (n < N);
        wptr[i] = wok[i] ? ((const float2*)(W + (size_t)n * K) + kp) : (const float2*)W;
        woff[i] = ((m >> 3) * 32 + (m & 7) * 4 + (kp & 3)) * 2 + (kp >> 2);
    }

    float acc[2][8][4];
#pragma unroll
    for (int mt = 0; mt < 2; mt++)
#pragma unroll
        for (int nt = 0; nt < 8; nt++)
#pragma unroll
            for (int q = 0; q < 4; q++) acc[mt][nt][q] = 0.f;

    const int nch = K >> 4;

    uint32_t rAh[4], rAl[4], rWh[4], rWl[4];

    // ---- stage chunk 0 into regs ----
#pragma unroll
    for (int i = 0; i < 4; i++) {
        float2 v = aptr[i][0];
        if (DO_T) {
            float2 sc = ((const float2*)scale)[kpv[i]];
            float2 sh = ((const float2*)shift)[kpv[i]];
            v.x = fmaxf(fmaf(v.x, sc.x, sh.x), 0.f);
            v.y = fmaxf(fmaf(v.y, sc.y, sh.y), 0.f);
        }
        float hx = __bfloat162float(__float2bfloat16_rn(v.x));
        float hy = __bfloat162float(__float2bfloat16_rn(v.y));
        rAh[i] = pack_bf2(v.x, v.y);
        rAl[i] = pack_bf2(v.x - hx, v.y - hy);
        float2 wv = wok[i] ? wptr[i][0] : make_float2(0.f, 0.f);
        float whx = __bfloat162float(__float2bfloat16_rn(wv.x));
        float why = __bfloat162float(__float2bfloat16_rn(wv.y));
        rWh[i] = pack_bf2(wv.x, wv.y);
        rWl[i] = pack_bf2(wv.x - whx, wv.y - why);
    }
    {
        uint32_t* pAh = &sAh[0][0][0][0];
        uint32_t* pAl = &sAl[0][0][0][0];
        uint32_t* pBh = &sBh[0][0][0][0];
        uint32_t* pBl = &sBl[0][0][0][0];
#pragma unroll
        for (int i = 0; i < 4; i++) {
            pAh[aoff[i]] = rAh[i];
            pAl[aoff[i]] = rAl[i];
            pBh[woff[i]] = rWh[i];
            pBl[woff[i]] = rWl[i];
        }
    }
    __syncthreads();

    for (int s = 0; s < nch; s++) {
        const int cur = s & 1;
        const int kq = (s + 1) << 3;    // float2 offset of next chunk

        // prefetch + convert next chunk into regs
        if (s + 1 < nch) {
#pragma unroll
            for (int i = 0; i < 4; i++) {
                float2 v = aptr[i][kq];
                if (DO_T) {
                    float2 sc = ((const float2*)scale)[kq + kpv[i]];
                    float2 sh = ((const float2*)shift)[kq + kpv[i]];
                    v.x = fmaxf(fmaf(v.x, sc.x, sh.x), 0.f);
                    v.y = fmaxf(fmaf(v.y, sc.y, sh.y), 0.f);
                }
                float hx = __bfloat162float(__float2bfloat16_rn(v.x));
                float hy = __bfloat162float(__float2bfloat16_rn(v.y));
                rAh[i] = pack_bf2(v.x, v.y);
                rAl[i] = pack_bf2(v.x - hx, v.y - hy);
                float2 wv = wok[i] ? wptr[i][kq] : make_float2(0.f, 0.f);
                float whx = __bfloat162float(__float2bfloat16_rn(wv.x));
                float why = __bfloat162float(__float2bfloat16_rn(wv.y));
                rWh[i] = pack_bf2(wv.x, wv.y);
                rWl[i] = pack_bf2(wv.x - whx, wv.y - why);
            }
        }

        // ---- MMA on current buffer ----
        {
            uint32_t ah[2][4], al[2][4];
#pragma unroll
            for (int mt = 0; mt < 2; mt++) {
                uint4 t0 = *(const uint4*)&sAh[cur][wm * 2 + mt][lane][0];
                ah[mt][0] = t0.x; ah[mt][1] = t0.y; ah[mt][2] = t0.z; ah[mt][3] = t0.w;
                uint4 t1 = *(const uint4*)&sAl[cur][wm * 2 + mt][lane][0];
                al[mt][0] = t1.x; al[mt][1] = t1.y; al[mt][2] = t1.z; al[mt][3] = t1.w;
            }
#pragma unroll
            for (int nt = 0; nt < 8; nt++) {
                uint2 bh2 = *(const uint2*)&sBh[cur][wn * 8 + nt][lane][0];
                uint2 bl2 = *(const uint2*)&sBl[cur][wn * 8 + nt][lane][0];
                uint32_t bh[2] = {bh2.x, bh2.y};
                uint32_t bl[2] = {bl2.x, bl2.y};
#pragma unroll
                for (int mt = 0; mt < 2; mt++) {
                    mma_bf16(acc[mt][nt], ah[mt], bh);
                    mma_bf16(acc[mt][nt], ah[mt], bl);
                    mma_bf16(acc[mt][nt], al[mt], bh);
                }
            }
        }

        // ---- write next chunk to the other buffer ----
        if (s + 1 < nch) {
            const int nxt = cur ^ 1;
            uint32_t* pAh = &sAh[nxt][0][0][0];
            uint32_t* pAl = &sAl[nxt][0][0][0];
            uint32_t* pBh = &sBh[nxt][0][0][0];
            uint32_t* pBl = &sBl[nxt][0][0][0];
#pragma unroll
            for (int i = 0; i < 4; i++) {
                pAh[aoff[i]] = rAh[i];
                pAl[aoff[i]] = rAl[i];
                pBh[woff[i]] = rWh[i];
                pBl[woff[i]] = rWl[i];
            }
            __syncthreads();
        }
    }

    // ---- epilogue: bias, store (float2), fused column stats ----
    const int l4 = lane >> 2;
    const int ln = lane & 3;
#pragma unroll
    for (int nt = 0; nt < 8; nt++) {
        const int colb = wn * 64 + nt * 8 + ln * 2;   // col within block
        const int col = bn0 + colb;
        const bool ok = (col < N);
        float b0 = ok ? bias[col] : 0.f;
        float b1 = ok ? bias[col + 1] : 0.f;
        float cs0 = 0.f, cs1 = 0.f, cq0 = 0.f, cq1 = 0.f;
#pragma unroll
        for (int mt = 0; mt < 2; mt++) {
            float c0 = acc[mt][nt][0] + b0;
            float c1 = acc[mt][nt][1] + b1;
            float c2 = acc[mt][nt][2] + b0;
            float c3 = acc[mt][nt][3] + b1;
            const int row = bm0 + wm * 32 + mt * 16 + l4;
            if (ok) {
                *(float2*)(C + (size_t)row * N + col)       = make_float2(c0, c1);
                *(float2*)(C + (size_t)(row + 8) * N + col) = make_float2(c2, c3);
            }
            if (DO_STATS) {
                cs0 += c0 + c2; cs1 += c1 + c3;
                cq0 += c0 * c0 + c2 * c2; cq1 += c1 * c1 + c3 * c3;
            }
        }
        if (DO_STATS) {
#pragma unroll
            for (int o = 4; o < 32; o <<= 1) {
                cs0 += __shfl_xor_sync(0xffffffffu, cs0, o);
                cs1 += __shfl_xor_sync(0xffffffffu, cs1, o);
                cq0 += __shfl_xor_sync(0xffffffffu, cq0, o);
                cq1 += __shfl_xor_sync(0xffffffffu, cq1, o);
            }
            if (l4 == 0) {
                atomicAdd(&s_sum[colb], cs0);
                atomicAdd(&s_sum[colb + 1], cs1);
                atomicAdd(&s_sq[colb], cq0);
                atomicAdd(&s_sq[colb + 1], cq1);
            }
        }
    }

    if (DO_STATS) {
        __syncthreads();
        if (tid < 128) {
            int n = bn0 + tid;
            if (n < N) {
                atomicAdd(&sums[n],     s_sum[tid]);
                atomicAdd(&sums[N + n], s_sq[tid]);
            }
        }
    }
}

// ---------------- finalize BN affine ----------------------------------------
__global__ void finalize_bn_kernel(const float* __restrict__ sums,
                                   const float* __restrict__ gamma,
                                   const float* __restrict__ beta,
                                   float* __restrict__ scale,
                                   float* __restrict__ shift,
                                   int N, float invM)
{
    int c = blockIdx.x * blockDim.x + threadIdx.x;
    if (c < N) {
        float m = sums[c] * invM;
        float v = sums[N + c] * invM - m * m;
        float sc = gamma[c] * rsqrtf(v + EPSBN);
        scale[c] = sc;
        shift[c] = beta[c] - m * sc;
    }
}

// ---------------- GRU recurrence (one warp per (batch, direction)) ----------
__global__ __launch_bounds__(32) void gru_kernel(
    const float* __restrict__ xp_f, const float* __restrict__ xp_b,
    const float* __restrict__ Whh_f, const float* __restrict__ bhh_f,
    const float* __restrict__ Whh_b, const float* __restrict__ bhh_b,
    float* __restrict__ gru_out)
{
    int b = blockIdx.x;
    int dir = blockIdx.y;
    int j = threadIdx.x;

    const float* xp  = dir ? xp_b  : xp_f;
    const float* Whh = dir ? Whh_b : Whh_f;
    const float* bhh = dir ? bhh_b : bhh_f;

    float Wr[32], Wz[32], Wn[32];
#pragma unroll
    for (int k = 0; k < 32; k++) {
        Wr[k] = Whh[j * 32 + k];
        Wz[k] = Whh[(32 + j) * 32 + k];
        Wn[k] = Whh[(64 + j) * 32 + k];
    }
    float br = bhh[j], bz = bhh[32 + j], bnn = bhh[64 + j];

    float h = 0.f;
    const int st = dir ? -96 : 96;
    int tcur = dir ? (TT - 1) : 0;
    const float* cur = xp + (size_t)b * TT * 96 + (size_t)tcur * 96;
    const float* pf = cur + 4 * st;
    float* outp = gru_out + ((size_t)b * TT + tcur) * 64 + dir * 32 + j;
    const long ost = dir ? -64 : 64;

    float fr[4], fz[4], fn[4];
#pragma unroll
    for (int q = 0; q < 4; q++) {
        const float* p = cur + q * st;
        fr[q] = p[j]; fz[q] = p[32 + j]; fn[q] = p[64 + j];
    }

    for (int it = 0; it < TT; it += 4) {
        float nfr[4], nfz[4], nfn[4];
        const bool more = (it + 4 < TT);
        if (more) {
#pragma unroll
            for (int q = 0; q < 4; q++) {
                const float* p = pf + q * st;
                nfr[q] = p[j]; nfz[q] = p[32 + j]; nfn[q] = p[64 + j];
            }
        }
        pf += 4 * st;

#pragma unroll
        for (int u = 0; u < 4; u++) {
            float ar0 = 0.f, ar1 = 0.f, ar2 = 0.f, ar3 = 0.f;
            float az0 = 0.f, az1 = 0.f, az2 = 0.f, az3 = 0.f;
            float an0 = 0.f, an1 = 0.f, an2 = 0.f, an3 = 0.f;
#pragma unroll
            for (int k = 0; k < 8; k++) {
                float h0 = __shfl_sync(0xffffffffu, h, k);
                float h1 = __shfl_sync(0xffffffffu, h, k + 8);
                float h2 = __shfl_sync(0xffffffffu, h, k + 16);
                float h3 = __shfl_sync(0xffffffffu, h, k + 24);
                ar0 = fmaf(Wr[k], h0, ar0);
                ar1 = fmaf(Wr[k + 8], h1, ar1);
                ar2 = fmaf(Wr[k + 16], h2, ar2);
                ar3 = fmaf(Wr[k + 24], h3, ar3);
                az0 = fmaf(Wz[k], h0, az0);
                az1 = fmaf(Wz[k + 8], h1, az1);
                az2 = fmaf(Wz[k + 16], h2, az2);
                az3 = fmaf(Wz[k + 24], h3, az3);
                an0 = fmaf(Wn[k], h0, an0);
                an1 = fmaf(Wn[k + 8], h1, an1);
                an2 = fmaf(Wn[k + 16], h2, an2);
                an3 = fmaf(Wn[k + 24], h3, an3);
            }
            float accr = br + (ar0 + ar1) + (ar2 + ar3);
            float accz = bz + (az0 + az1) + (az2 + az3);
            float accn = bnn + (an0 + an1) + (an2 + an3);
            float r = 1.f / (1.f + __expf(-(fr[u] + accr)));
            float z = 1.f / (1.f + __expf(-(fz[u] + accz)));
            float pre = fn[u] + r * accn;
            float n = 1.f - 2.f / (__expf(2.f * pre) + 1.f);
            h = (1.f - z) * n + z * h;
            *outp = h;
            outp += ost;
        }
#pragma unroll
        for (int q = 0; q < 4; q++) { fr[q] = nfr[q]; fz[q] = nfz[q]; fn[q] = nfn[q]; }
    }
}

// ---------------- attention + softmax pooling (one block per batch) ---------
__global__ __launch_bounds__(256) void attn_kernel(
    const float* __restrict__ gru,
    const float* __restrict__ Wa1, const float* __restrict__ ba1,
    const float* __restrict__ Wa2, const float* __restrict__ ba2,
    float* __restrict__ pooled)
{
    __shared__ float s_scores[TT];
    __shared__ float s_Wa1[32 * 64];
    __shared__ float s_red[8];
    __shared__ float s_bcast[2];
    __shared__ float s_pool[4][64];

    int b = blockIdx.x;
    int tid = threadIdx.x;
    int lane = tid & 31;
    int w = tid >> 5;

    for (int i = tid; i < 32 * 64; i += 256) s_Wa1[i] = Wa1[i];
    __syncthreads();

    const float* gb = gru + (size_t)b * TT * 64;
    float wa2 = Wa2[lane];
    float ba2v = ba2[0];
    float ba1v = ba1[lane];

    for (int t = w; t < TT; t += 8) {
        const float* g = gb + (size_t)t * 64;
        float acc = ba1v;
#pragma unroll
        for (int k = 0; k < 64; k++) acc += s_Wa1[lane * 64 + k] * g[k];
        float v = tanhf(acc) * wa2;
#pragma unroll
        for (int o = 16; o; o >>= 1) v += __shfl_xor_sync(0xffffffffu, v, o);
        if (lane == 0) s_scores[t] = v + ba2v;
    }
    __syncthreads();

    float m = -1e30f;
    for (int t = tid; t < TT; t += 256) m = fmaxf(m, s_scores[t]);
#pragma unroll
    for (int o = 16; o; o >>= 1) m = fmaxf(m, __shfl_xor_sync(0xffffffffu, m, o));
    if (lane == 0) s_red[w] = m;
    __syncthreads();
    if (tid == 0) {
        float mm = s_red[0];
#pragma unroll
        for (int i = 1; i < 8; i++) mm = fmaxf(mm, s_red[i]);
        s_bcast[0] = mm;
    }
    __syncthreads();
    m = s_bcast[0];

    float sum = 0.f;
    for (int t = tid; t < TT; t += 256) {
        float e = __expf(s_scores[t] - m);
        s_scores[t] = e;
        sum += e;
    }
#pragma unroll
    for (int o = 16; o; o >>= 1) sum += __shfl_xor_sync(0xffffffffu, sum, o);
    if (lane == 0) s_red[w] = sum;
    __syncthreads();
    if (tid == 0) {
        float ss = 0.f;
#pragma unroll
        for (int i = 0; i < 8; i++) ss += s_red[i];
        s_bcast[1] = ss;
    }
    __syncthreads();
    float sumexp = s_bcast[1];

    int c = tid & 63;
    int grp = tid >> 6;
    float acc = 0.f;
    for (int t = grp; t < TT; t += 4) acc += s_scores[t] * gb[(size_t)t * 64 + c];
    s_pool[grp][c] = acc;
    __syncthreads();
    if (tid < 64) {
        float tot = s_pool[0][tid] + s_pool[1][tid] + s_pool[2][tid] + s_pool[3][tid];
        pooled[b * 64 + tid] = tot / sumexp;
    }
}

// ---------------- classifier -------------------------------------------------
__global__ __launch_bounds__(128) void cls_kernel(
    const float* __restrict__ pooled,
    const float* __restrict__ Wc1, const float* __restrict__ bc1,
    const float* __restrict__ gc, const float* __restrict__ bec,
    const float* __restrict__ Wc2, const float* __restrict__ bc2,
    float* __restrict__ out)
{
    __shared__ float s_sum[32], s_sq[32], s_scale[32], s_shift[32];
    int r = threadIdx.x;
    if (r < 32) { s_sum[r] = 0.f; s_sq[r] = 0.f; }
    __syncthreads();

    float x[64];
#pragma unroll
    for (int k = 0; k < 64; k++) x[k] = pooled[r * 64 + k];

    float q[32];
#pragma unroll
    for (int u = 0; u < 32; u++) {
        float a = bc1[u];
#pragma unroll
        for (int k = 0; k < 64; k++) a += Wc1[u * 64 + k] * x[k];
        q[u] = a;
        atomicAdd(&s_sum[u], a);
        atomicAdd(&s_sq[u], a * a);
    }
    __syncthreads();
    if (r < 32) {
        float m = s_sum[r] * (1.f / 128.f);
        float v = s_sq[r] * (1.f / 128.f) - m * m;
        float sc = gc[r] * rsqrtf(v + EPSBN);
        s_scale[r] = sc;
        s_shift[r] = bec[r] - m * sc;
    }
    __syncthreads();

    float qn[32];
#pragma unroll
    for (int u = 0; u < 32; u++) {
        float t = q[u] * s_scale[u] + s_shift[u];
        qn[u] = t > 0.f ? t : 0.f;
    }
#pragma unroll
    for (int c = 0; c < NCLS; c++) {
        float a = bc2[c];
#pragma unroll
        for (int k = 0; k < 32; k++) a += Wc2[c * 32 + k] * qn[k];
        out[r * NCLS + c] = a;
    }
}

// ---------------- launch ----------------------------------------------------
extern "C" void kernel_launch(void* const* d_in, const int* in_sizes, int n_in,
                              void* d_out, int out_size)
{
    (void)in_sizes; (void)n_in; (void)out_size;

    const float* x     = (const float*)d_in[0];
    const float* W1    = (const float*)d_in[1];
    const float* b1    = (const float*)d_in[2];
    const float* g1    = (const float*)d_in[3];
    const float* be1   = (const float*)d_in[4];
    const float* W2    = (const float*)d_in[5];
    const float* b2    = (const float*)d_in[6];
    const float* g2    = (const float*)d_in[7];
    const float* be2   = (const float*)d_in[8];
    const float* W3    = (const float*)d_in[9];
    const float* b3    = (const float*)d_in[10];
    const float* g3    = (const float*)d_in[11];
    const float* be3   = (const float*)d_in[12];
    const float* Wih_f = (const float*)d_in[13];
    const float* Whh_f = (const float*)d_in[14];
    const float* bih_f = (const float*)d_in[15];
    const float* bhh_f = (const float*)d_in[16];
    const float* Wih_b = (const float*)d_in[17];
    const float* Whh_b = (const float*)d_in[18];
    const float* bih_b = (const float*)d_in[19];
    const float* bhh_b = (const float*)d_in[20];
    const float* Wa1   = (const float*)d_in[21];
    const float* ba1   = (const float*)d_in[22];
    const float* Wa2   = (const float*)d_in[23];
    const float* ba2   = (const float*)d_in[24];
    const float* Wc1   = (const float*)d_in[25];
    const float* bc1   = (const float*)d_in[26];
    const float* gc    = (const float*)d_in[27];
    const float* bec   = (const float*)d_in[28];
    const float* Wc2   = (const float*)d_in[29];
    const float* bc2   = (const float*)d_in[30];
    float* out = (float*)d_out;

    float *y1, *y2, *y3, *xpf, *xpb, *gru, *pooled;
    float *sums1, *sums2, *sums3, *sc1, *sh1, *sc2, *sh2, *sc3, *sh3;
    cudaGetSymbolAddress((void**)&y1, g_y1);
    cudaGetSymbolAddress((void**)&y2, g_y2);
    cudaGetSymbolAddress((void**)&y3, g_y3);
    cudaGetSymbolAddress((void**)&xpf, g_xpf);
    cudaGetSymbolAddress((void**)&xpb, g_xpb);
    cudaGetSymbolAddress((void**)&gru, g_gru);
    cudaGetSymbolAddress((void**)&pooled, g_pooled);
    cudaGetSymbolAddress((void**)&sums1, g_sums1);
    cudaGetSymbolAddress((void**)&sums2, g_sums2);
    cudaGetSymbolAddress((void**)&sums3, g_sums3);
    cudaGetSymbolAddress((void**)&sc1, g_sc1);
    cudaGetSymbolAddress((void**)&sh1, g_sh1);
    cudaGetSymbolAddress((void**)&sc2, g_sc2);
    cudaGetSymbolAddress((void**)&sh2, g_sh2);
    cudaGetSymbolAddress((void**)&sc3, g_sc3);
    cudaGetSymbolAddress((void**)&sh3, g_sh3);

    const float invM = 1.f / (float)MROWS;
    const int gx = MROWS / 128;

    zero_stats_kernel<<<1, 512>>>(sums1, sums2, sums3);

    // L1: y1 = x @ W1^T + b1     (N=256, K=80) + fused column stats
    bgemm_kernel<0,1><<<dim3(gx, 2), 256>>>(x, W1, b1, nullptr, nullptr,
                                            y1, sums1, MROWS, 256, FF);
    finalize_bn_kernel<<<1, 256>>>(sums1, g1, be1, sc1, sh1, 256, invM);

    // L2: y2 = relu(bn1(y1)) @ W2^T + b2   (N=128, K=256)
    bgemm_kernel<1,1><<<dim3(gx, 1), 256>>>(y1, W2, b2, sc1, sh1,
                                            y2, sums2, MROWS, 128, 256);
    finalize_bn_kernel<<<1, 128>>>(sums2, g2, be2, sc2, sh2, 128, invM);

    // L3: y3 = relu(bn2(y2)) @ W3^T + b3   (N=64, K=128)
    bgemm_kernel<1,1><<<dim3(gx, 1), 256>>>(y2, W3, b3, sc2, sh2,
                                            y3, sums3, MROWS, 64, 128);
    finalize_bn_kernel<<<1, 64>>>(sums3, g3, be3, sc3, sh3, 64, invM);

    // GRU input projections: xp = relu(bn3(y3)) @ Wih^T + bih   (N=96, K=64)
    bgemm_kernel<1,0><<<dim3(gx, 1), 256>>>(y3, Wih_f, bih_f, sc3, sh3,
                                            xpf, nullptr, MROWS, 96, 64);
    bgemm_kernel<1,0><<<dim3(gx, 1), 256>>>(y3, Wih_b, bih_b, sc3, sh3,
                                            xpb, nullptr, MROWS, 96, 64);

    // GRU recurrence
    gru_kernel<<<dim3(BB, 2), 32>>>(xpf, xpb, Whh_f, bhh_f, Whh_b, bhh_b, gru);

    // attention pooling
    attn_kernel<<<BB, 256>>>(gru, Wa1, ba1, Wa2, ba2, pooled);

    // classifier
    cls_kernel<<<1, 128>>>(pooled, Wc1, bc1, gc, bec, Wc2, bc2, out);
}

// round 6
// speedup vs baseline: 3.1083x; 1.3081x over previous
#include <cuda_runtime.h>
#include <cuda_bf16.h>
#include <stdint.h>
#include <math.h>

// Problem constants
#define BB 128
#define TT 2048
#define FF 80
#define NCLS 10
#define HH 32
#define MROWS (BB*TT)          // 262144
#define EPSBN 1e-5f

// ---------------- scratch (static __device__ arrays; no allocation) -------
__device__ float g_y1[(size_t)MROWS * 256];
__device__ float g_y2[(size_t)MROWS * 128];
__device__ float g_y3[(size_t)MROWS * 64];
__device__ float g_xpf[(size_t)MROWS * 96];
__device__ float g_xpb[(size_t)MROWS * 96];
__device__ float g_gru[(size_t)MROWS * 64];
__device__ float g_pooled[BB * 64];
__device__ float g_sums1[512];
__device__ float g_sums2[256];
__device__ float g_sums3[128];
__device__ float g_sc1[256], g_sh1[256];
__device__ float g_sc2[128], g_sh2[128];
__device__ float g_sc3[64],  g_sh3[64];

__global__ void zero_stats_kernel(float* s1, float* s2, float* s3) {
    int i = threadIdx.x;
    if (i < 512) s1[i] = 0.f;
    if (i < 256) s2[i] = 0.f;
    if (i < 128) s3[i] = 0.f;
}

// ---------------- helpers ----------------------------------------------------
__device__ __forceinline__ uint32_t pack_bf2(float x, float y) {
    unsigned short h0 = __bfloat16_as_ushort(__float2bfloat16_rn(x));
    unsigned short h1 = __bfloat16_as_ushort(__float2bfloat16_rn(y));
    return (uint32_t)h0 | ((uint32_t)h1 << 16);
}

__device__ __forceinline__ void mma_bf16(float* c, const uint32_t* a, const uint32_t* b) {
    asm volatile(
        "mma.sync.aligned.m16n8k16.row.col.f32.bf16.bf16.f32 "
        "{%0,%1,%2,%3}, {%4,%5,%6,%7}, {%8,%9}, {%0,%1,%2,%3};"
        : "+f"(c[0]), "+f"(c[1]), "+f"(c[2]), "+f"(c[3])
        : "r"(a[0]), "r"(a[1]), "r"(a[2]), "r"(a[3]), "r"(b[0]), "r"(b[1]));
}

__device__ __forceinline__ void packf2(unsigned long long& d, float lo, float hi) {
    asm("mov.b64 %0, {%1, %2};" : "=l"(d) : "f"(lo), "f"(hi));
}
__device__ __forceinline__ float sumf2(unsigned long long v) {
    float lo, hi;
    asm("mov.b64 {%0, %1}, %2;" : "=f"(lo), "=f"(hi) : "l"(v));
    return lo + hi;
}
__device__ __forceinline__ void fma2(unsigned long long& d,
                                     unsigned long long a, unsigned long long b) {
    asm("fma.rn.f32x2 %0, %1, %2, %0;" : "+l"(d) : "l"(a), "l"(b));
}

// =====================================================================
// BGEMM (tensor-core, bf16 hi/lo split): C[M,N] = f(A[M,K]) @ W[N,K]^T + bias
// NARROW=0: BM=128,BN=128, 8 warps as 4x2.  NARROW=1: BM=128,BN=64, 8 warps
// as 8x1 (each warp 16 rows x 64 cols) — for N<=64 layers.
// C = Ah*Wh + Ah*Wl + Al*Wh (error ~2^-16). DO_STATS: fused column stats.
// =====================================================================
template<int DO_T, int DO_STATS, int NARROW>
__global__ __launch_bounds__(256, 2) void bgemm_kernel(
    const float* __restrict__ A, const float* __restrict__ W,
    const float* __restrict__ bias,
    const float* __restrict__ scale, const float* __restrict__ shift,
    float* __restrict__ C, float* __restrict__ sums,
    int M, int N, int K)
{
    __shared__ __align__(16) uint32_t sAh[2][8][32][4];
    __shared__ __align__(16) uint32_t sAl[2][8][32][4];
    __shared__ __align__(16) uint32_t sBh[2][16][32][2];
    __shared__ __align__(16) uint32_t sBl[2][16][32][2];
    __shared__ float s_sum[128], s_sq[128];

    const int tid = threadIdx.x;
    const int lane = tid & 31;
    const int wid = tid >> 5;
    const int wm = NARROW ? wid : (wid & 3);
    const int wn = NARROW ? 0 : (wid >> 2);
    const int MT = NARROW ? 1 : 2;
    const int bm0 = blockIdx.x * 128;
    const int bn0 = blockIdx.y * 128;

    if (DO_STATS && tid < 128) { s_sum[tid] = 0.f; s_sq[tid] = 0.f; }

    // ---- per-thread staging mappings (4 passes, 4 fp32-pairs each) ----
    const float2* aptr[4];
    const float2* wptr[4];
    int aoff[4], woff[4];
    bool wok[4];
    int kpv[4];
#pragma unroll
    for (int i = 0; i < 4; i++) {
        int p = tid + i * 256;
        int m = p >> 3;
        int kp = p & 7;
        kpv[i] = kp;
        aptr[i] = (const float2*)(A + (size_t)(bm0 + m) * K) + kp;
        int mt = m >> 4, r = m & 15;
        aoff[i] = ((mt * 32) + (r & 7) * 4 + (kp & 3)) * 4 + ((r >> 3) + 2 * (kp >> 2));
        int n = bn0 + m;
        wok[i] = (n < N);
        wptr[i] = wok[i] ? ((const float2*)(W + (size_t)n * K) + kp) : (const float2*)W;
        woff[i] = ((m >> 3) * 32 + (m & 7) * 4 + (kp & 3)) * 2 + (kp >> 2);
    }

    float acc[2][8][4];
#pragma unroll
    for (int mt = 0; mt < 2; mt++)
#pragma unroll
        for (int nt = 0; nt < 8; nt++)
#pragma unroll
            for (int q = 0; q < 4; q++) acc[mt][nt][q] = 0.f;

    const int nch = K >> 4;

    uint32_t rAh[4], rAl[4], rWh[4], rWl[4];

    // ---- stage chunk 0 ----
#pragma unroll
    for (int i = 0; i < 4; i++) {
        float2 v = aptr[i][0];
        if (DO_T) {
            float2 sc = ((const float2*)scale)[kpv[i]];
            float2 sh = ((const float2*)shift)[kpv[i]];
            v.x = fmaxf(fmaf(v.x, sc.x, sh.x), 0.f);
            v.y = fmaxf(fmaf(v.y, sc.y, sh.y), 0.f);
        }
        float hx = __bfloat162float(__float2bfloat16_rn(v.x));
        float hy = __bfloat162float(__float2bfloat16_rn(v.y));
        rAh[i] = pack_bf2(v.x, v.y);
        rAl[i] = pack_bf2(v.x - hx, v.y - hy);
        float2 wv = wok[i] ? wptr[i][0] : make_float2(0.f, 0.f);
        float whx = __bfloat162float(__float2bfloat16_rn(wv.x));
        float why = __bfloat162float(__float2bfloat16_rn(wv.y));
        rWh[i] = pack_bf2(wv.x, wv.y);
        rWl[i] = pack_bf2(wv.x - whx, wv.y - why);
    }
    {
        uint32_t* pAh = &sAh[0][0][0][0];
        uint32_t* pAl = &sAl[0][0][0][0];
        uint32_t* pBh = &sBh[0][0][0][0];
        uint32_t* pBl = &sBl[0][0][0][0];
#pragma unroll
        for (int i = 0; i < 4; i++) {
            pAh[aoff[i]] = rAh[i];
            pAl[aoff[i]] = rAl[i];
            pBh[woff[i]] = rWh[i];
            pBl[woff[i]] = rWl[i];
        }
    }
    __syncthreads();

    for (int s = 0; s < nch; s++) {
        const int cur = s & 1;
        const int kq = (s + 1) << 3;

        if (s + 1 < nch) {
#pragma unroll
            for (int i = 0; i < 4; i++) {
                float2 v = aptr[i][kq];
                if (DO_T) {
                    float2 sc = ((const float2*)scale)[kq + kpv[i]];
                    float2 sh = ((const float2*)shift)[kq + kpv[i]];
                    v.x = fmaxf(fmaf(v.x, sc.x, sh.x), 0.f);
                    v.y = fmaxf(fmaf(v.y, sc.y, sh.y), 0.f);
                }
                float hx = __bfloat162float(__float2bfloat16_rn(v.x));
                float hy = __bfloat162float(__float2bfloat16_rn(v.y));
                rAh[i] = pack_bf2(v.x, v.y);
                rAl[i] = pack_bf2(v.x - hx, v.y - hy);
                float2 wv = wok[i] ? wptr[i][kq] : make_float2(0.f, 0.f);
                float whx = __bfloat162float(__float2bfloat16_rn(wv.x));
                float why = __bfloat162float(__float2bfloat16_rn(wv.y));
                rWh[i] = pack_bf2(wv.x, wv.y);
                rWl[i] = pack_bf2(wv.x - whx, wv.y - why);
            }
        }

        // ---- MMA on current buffer ----
        {
            uint32_t ah[2][4], al[2][4];
#pragma unroll
            for (int mt = 0; mt < MT; mt++) {
                const int mtile = NARROW ? wm : (wm * 2 + mt);
                uint4 t0 = *(const uint4*)&sAh[cur][mtile][lane][0];
                ah[mt][0] = t0.x; ah[mt][1] = t0.y; ah[mt][2] = t0.z; ah[mt][3] = t0.w;
                uint4 t1 = *(const uint4*)&sAl[cur][mtile][lane][0];
                al[mt][0] = t1.x; al[mt][1] = t1.y; al[mt][2] = t1.z; al[mt][3] = t1.w;
            }
#pragma unroll
            for (int nt = 0; nt < 8; nt++) {
                uint2 bh2 = *(const uint2*)&sBh[cur][wn * 8 + nt][lane][0];
                uint2 bl2 = *(const uint2*)&sBl[cur][wn * 8 + nt][lane][0];
                uint32_t bh[2] = {bh2.x, bh2.y};
                uint32_t bl[2] = {bl2.x, bl2.y};
#pragma unroll
                for (int mt = 0; mt < MT; mt++) {
                    mma_bf16(acc[mt][nt], ah[mt], bh);
                    mma_bf16(acc[mt][nt], ah[mt], bl);
                    mma_bf16(acc[mt][nt], al[mt], bh);
                }
            }
        }

        if (s + 1 < nch) {
            const int nxt = cur ^ 1;
            uint32_t* pAh = &sAh[nxt][0][0][0];
            uint32_t* pAl = &sAl[nxt][0][0][0];
            uint32_t* pBh = &sBh[nxt][0][0][0];
            uint32_t* pBl = &sBl[nxt][0][0][0];
#pragma unroll
            for (int i = 0; i < 4; i++) {
                pAh[aoff[i]] = rAh[i];
                pAl[aoff[i]] = rAl[i];
                pBh[woff[i]] = rWh[i];
                pBl[woff[i]] = rWl[i];
            }
            __syncthreads();
        }
    }

    // ---- epilogue ----
    const int l4 = lane >> 2;
    const int ln = lane & 3;
#pragma unroll
    for (int nt = 0; nt < 8; nt++) {
        const int colb = wn * 64 + nt * 8 + ln * 2;
        const int col = bn0 + colb;
        const bool ok = (col < N);
        float b0 = ok ? bias[col] : 0.f;
        float b1 = ok ? bias[col + 1] : 0.f;
        float cs0 = 0.f, cs1 = 0.f, cq0 = 0.f, cq1 = 0.f;
#pragma unroll
        for (int mt = 0; mt < MT; mt++) {
            float c0 = acc[mt][nt][0] + b0;
            float c1 = acc[mt][nt][1] + b1;
            float c2 = acc[mt][nt][2] + b0;
            float c3 = acc[mt][nt][3] + b1;
            const int row = bm0 + (NARROW ? wm * 16 : wm * 32 + mt * 16) + l4;
            if (ok) {
                *(float2*)(C + (size_t)row * N + col)       = make_float2(c0, c1);
                *(float2*)(C + (size_t)(row + 8) * N + col) = make_float2(c2, c3);
            }
            if (DO_STATS) {
                cs0 += c0 + c2; cs1 += c1 + c3;
                cq0 += c0 * c0 + c2 * c2; cq1 += c1 * c1 + c3 * c3;
            }
        }
        if (DO_STATS) {
#pragma unroll
            for (int o = 4; o < 32; o <<= 1) {
                cs0 += __shfl_xor_sync(0xffffffffu, cs0, o);
                cs1 += __shfl_xor_sync(0xffffffffu, cs1, o);
                cq0 += __shfl_xor_sync(0xffffffffu, cq0, o);
                cq1 += __shfl_xor_sync(0xffffffffu, cq1, o);
            }
            if (l4 == 0) {
                atomicAdd(&s_sum[colb], cs0);
                atomicAdd(&s_sum[colb + 1], cs1);
                atomicAdd(&s_sq[colb], cq0);
                atomicAdd(&s_sq[colb + 1], cq1);
            }
        }
    }

    if (DO_STATS) {
        __syncthreads();
        if (tid < 128) {
            int n = bn0 + tid;
            if (n < N) {
                atomicAdd(&sums[n],     s_sum[tid]);
                atomicAdd(&sums[N + n], s_sq[tid]);
            }
        }
    }
}

// ---------------- finalize BN affine ----------------------------------------
__global__ void finalize_bn_kernel(const float* __restrict__ sums,
                                   const float* __restrict__ gamma,
                                   const float* __restrict__ beta,
                                   float* __restrict__ scale,
                                   float* __restrict__ shift,
                                   int N, float invM)
{
    int c = blockIdx.x * blockDim.x + threadIdx.x;
    if (c < N) {
        float m = sums[c] * invM;
        float v = sums[N + c] * invM - m * m;
        float sc = gamma[c] * rsqrtf(v + EPSBN);
        scale[c] = sc;
        shift[c] = beta[c] - m * sc;
    }
}

// ---------------- GRU recurrence (one warp per (batch, direction)) ----------
// depth-4 xp prefetch + packed f32x2 recurrent matvec
__global__ __launch_bounds__(32) void gru_kernel(
    const float* __restrict__ xp_f, const float* __restrict__ xp_b,
    const float* __restrict__ Whh_f, const float* __restrict__ bhh_f,
    const float* __restrict__ Whh_b, const float* __restrict__ bhh_b,
    float* __restrict__ gru_out)
{
    int b = blockIdx.x;
    int dir = blockIdx.y;
    int j = threadIdx.x;

    const float* xp  = dir ? xp_b  : xp_f;
    const float* Whh = dir ? Whh_b : Whh_f;
    const float* bhh = dir ? bhh_b : bhh_f;

    unsigned long long Wr2[16], Wz2[16], Wn2[16];
#pragma unroll
    for (int k2 = 0; k2 < 16; k2++) {
        packf2(Wr2[k2], Whh[j * 32 + 2 * k2],        Whh[j * 32 + 2 * k2 + 1]);
        packf2(Wz2[k2], Whh[(32 + j) * 32 + 2 * k2], Whh[(32 + j) * 32 + 2 * k2 + 1]);
        packf2(Wn2[k2], Whh[(64 + j) * 32 + 2 * k2], Whh[(64 + j) * 32 + 2 * k2 + 1]);
    }
    float br = bhh[j], bz = bhh[32 + j], bnn = bhh[64 + j];

    float h = 0.f;
    const int st = dir ? -96 : 96;
    int tcur = dir ? (TT - 1) : 0;
    const float* cur = xp + (size_t)b * TT * 96 + (size_t)tcur * 96;
    const float* pf = cur + 4 * st;
    float* outp = gru_out + ((size_t)b * TT + tcur) * 64 + dir * 32 + j;
    const long ost = dir ? -64 : 64;

    float fr[4], fz[4], fn[4];
#pragma unroll
    for (int q = 0; q < 4; q++) {
        const float* p = cur + q * st;
        fr[q] = p[j]; fz[q] = p[32 + j]; fn[q] = p[64 + j];
    }

    for (int it = 0; it < TT; it += 4) {
        float nfr[4], nfz[4], nfn[4];
        const bool more = (it + 4 < TT);
        if (more) {
#pragma unroll
            for (int q = 0; q < 4; q++) {
                const float* p = pf + q * st;
                nfr[q] = p[j]; nfz[q] = p[32 + j]; nfn[q] = p[64 + j];
            }
        }
        pf += 4 * st;

#pragma unroll
        for (int u = 0; u < 4; u++) {
            unsigned long long ra = 0ull, rb = 0ull;
            unsigned long long za = 0ull, zb = 0ull;
            unsigned long long na = 0ull, nb = 0ull;
#pragma unroll
            for (int k2 = 0; k2 < 16; k2++) {
                float h0 = __shfl_sync(0xffffffffu, h, 2 * k2);
                float h1 = __shfl_sync(0xffffffffu, h, 2 * k2 + 1);
                unsigned long long hp;
                packf2(hp, h0, h1);
                if (k2 & 1) {
                    fma2(rb, Wr2[k2], hp);
                    fma2(zb, Wz2[k2], hp);
                    fma2(nb, Wn2[k2], hp);
                } else {
                    fma2(ra, Wr2[k2], hp);
                    fma2(za, Wz2[k2], hp);
                    fma2(na, Wn2[k2], hp);
                }
            }
            float accr = br + sumf2(ra) + sumf2(rb);
            float accz = bz + sumf2(za) + sumf2(zb);
            float accn = bnn + sumf2(na) + sumf2(nb);
            float r = 1.f / (1.f + __expf(-(fr[u] + accr)));
            float z = 1.f / (1.f + __expf(-(fz[u] + accz)));
            float pre = fn[u] + r * accn;
            float n = 1.f - 2.f / (__expf(2.f * pre) + 1.f);
            h = (1.f - z) * n + z * h;
            *outp = h;
            outp += ost;
        }
#pragma unroll
        for (int q = 0; q < 4; q++) { fr[q] = nfr[q]; fz[q] = nfz[q]; fn[q] = nfn[q]; }
    }
}

// ---------------- attention + softmax pooling (one block per batch) ---------
// Score pass: lane u holds Wa1 row u in registers; g broadcast via shfl.
__global__ __launch_bounds__(256) void attn_kernel(
    const float* __restrict__ gru,
    const float* __restrict__ Wa1, const float* __restrict__ ba1,
    const float* __restrict__ Wa2, const float* __restrict__ ba2,
    float* __restrict__ pooled)
{
    __shared__ float s_scores[TT];
    __shared__ float s_red[8];
    __shared__ float s_bcast[2];
    __shared__ float s_pool[4][64];

    int b = blockIdx.x;
    int tid = threadIdx.x;
    int lane = tid & 31;
    int w = tid >> 5;

    // lane u = lane: Wa1 row in registers
    float wrow[64];
#pragma unroll
    for (int k = 0; k < 64; k++) wrow[k] = Wa1[lane * 64 + k];

    const float* gb = gru + (size_t)b * TT * 64;
    float wa2 = Wa2[lane];
    float ba2v = ba2[0];
    float ba1v = ba1[lane];

    for (int t = w; t < TT; t += 8) {
        const float* g = gb + (size_t)t * 64;
        float g0 = g[lane];
        float g1 = g[32 + lane];
        float a0 = ba1v, a1 = 0.f, a2 = 0.f, a3 = 0.f;
#pragma unroll
        for (int k = 0; k < 32; k += 4) {
            a0 = fmaf(wrow[k],     __shfl_sync(0xffffffffu, g0, k),     a0);
            a1 = fmaf(wrow[k + 1], __shfl_sync(0xffffffffu, g0, k + 1), a1);
            a2 = fmaf(wrow[k + 2], __shfl_sync(0xffffffffu, g0, k + 2), a2);
            a3 = fmaf(wrow[k + 3], __shfl_sync(0xffffffffu, g0, k + 3), a3);
        }
#pragma unroll
        for (int k = 0; k < 32; k += 4) {
            a0 = fmaf(wrow[32 + k],     __shfl_sync(0xffffffffu, g1, k),     a0);
            a1 = fmaf(wrow[32 + k + 1], __shfl_sync(0xffffffffu, g1, k + 1), a1);
            a2 = fmaf(wrow[32 + k + 2], __shfl_sync(0xffffffffu, g1, k + 2), a2);
            a3 = fmaf(wrow[32 + k + 3], __shfl_sync(0xffffffffu, g1, k + 3), a3);
        }
        float acc = (a0 + a1) + (a2 + a3);
        float v = tanhf(acc) * wa2;
#pragma unroll
        for (int o = 16; o; o >>= 1) v += __shfl_xor_sync(0xffffffffu, v, o);
        if (lane == 0) s_scores[t] = v + ba2v;
    }
    __syncthreads();

    float m = -1e30f;
    for (int t = tid; t < TT; t += 256) m = fmaxf(m, s_scores[t]);
#pragma unroll
    for (int o = 16; o; o >>= 1) m = fmaxf(m, __shfl_xor_sync(0xffffffffu, m, o));
    if (lane == 0) s_red[w] = m;
    __syncthreads();
    if (tid == 0) {
        float mm = s_red[0];
#pragma unroll
        for (int i = 1; i < 8; i++) mm = fmaxf(mm, s_red[i]);
        s_bcast[0] = mm;
    }
    __syncthreads();
    m = s_bcast[0];

    float sum = 0.f;
    for (int t = tid; t < TT; t += 256) {
        float e = __expf(s_scores[t] - m);
        s_scores[t] = e;
        sum += e;
    }
#pragma unroll
    for (int o = 16; o; o >>= 1) sum += __shfl_xor_sync(0xffffffffu, sum, o);
    if (lane == 0) s_red[w] = sum;
    __syncthreads();
    if (tid == 0) {
        float ss = 0.f;
#pragma unroll
        for (int i = 0; i < 8; i++) ss += s_red[i];
        s_bcast[1] = ss;
    }
    __syncthreads();
    float sumexp = s_bcast[1];

    int c = tid & 63;
    int grp = tid >> 6;
    float acc = 0.f;
    for (int t = grp; t < TT; t += 4) acc += s_scores[t] * gb[(size_t)t * 64 + c];
    s_pool[grp][c] = acc;
    __syncthreads();
    if (tid < 64) {
        float tot = s_pool[0][tid] + s_pool[1][tid] + s_pool[2][tid] + s_pool[3][tid];
        pooled[b * 64 + tid] = tot / sumexp;
    }
}

// ---------------- classifier -------------------------------------------------
__global__ __launch_bounds__(128) void cls_kernel(
    const float* __restrict__ pooled,
    const float* __restrict__ Wc1, const float* __restrict__ bc1,
    const float* __restrict__ gc, const float* __restrict__ bec,
    const float* __restrict__ Wc2, const float* __restrict__ bc2,
    float* __restrict__ out)
{
    __shared__ float s_sum[32], s_sq[32], s_scale[32], s_shift[32];
    int r = threadIdx.x;
    if (r < 32) { s_sum[r] = 0.f; s_sq[r] = 0.f; }
    __syncthreads();

    float x[64];
#pragma unroll
    for (int k = 0; k < 64; k++) x[k] = pooled[r * 64 + k];

    float q[32];
#pragma unroll
    for (int u = 0; u < 32; u++) {
        float a = bc1[u];
#pragma unroll
        for (int k = 0; k < 64; k++) a += Wc1[u * 64 + k] * x[k];
        q[u] = a;
        atomicAdd(&s_sum[u], a);
        atomicAdd(&s_sq[u], a * a);
    }
    __syncthreads();
    if (r < 32) {
        float m = s_sum[r] * (1.f / 128.f);
        float v = s_sq[r] * (1.f / 128.f) - m * m;
        float sc = gc[r] * rsqrtf(v + EPSBN);
        s_scale[r] = sc;
        s_shift[r] = bec[r] - m * sc;
    }
    __syncthreads();

    float qn[32];
#pragma unroll
    for (int u = 0; u < 32; u++) {
        float t = q[u] * s_scale[u] + s_shift[u];
        qn[u] = t > 0.f ? t : 0.f;
    }
#pragma unroll
    for (int c = 0; c < NCLS; c++) {
        float a = bc2[c];
#pragma unroll
        for (int k = 0; k < 32; k++) a += Wc2[c * 32 + k] * qn[k];
        out[r * NCLS + c] = a;
    }
}

// ---------------- launch ----------------------------------------------------
extern "C" void kernel_launch(void* const* d_in, const int* in_sizes, int n_in,
                              void* d_out, int out_size)
{
    (void)in_sizes; (void)n_in; (void)out_size;

    const float* x     = (const float*)d_in[0];
    const float* W1    = (const float*)d_in[1];
    const float* b1    = (const float*)d_in[2];
    const float* g1    = (const float*)d_in[3];
    const float* be1   = (const float*)d_in[4];
    const float* W2    = (const float*)d_in[5];
    const float* b2    = (const float*)d_in[6];
    const float* g2    = (const float*)d_in[7];
    const float* be2   = (const float*)d_in[8];
    const float* W3    = (const float*)d_in[9];
    const float* b3    = (const float*)d_in[10];
    const float* g3    = (const float*)d_in[11];
    const float* be3   = (const float*)d_in[12];
    const float* Wih_f = (const float*)d_in[13];
    const float* Whh_f = (const float*)d_in[14];
    const float* bih_f = (const float*)d_in[15];
    const float* bhh_f = (const float*)d_in[16];
    const float* Wih_b = (const float*)d_in[17];
    const float* Whh_b = (const float*)d_in[18];
    const float* bih_b = (const float*)d_in[19];
    const float* bhh_b = (const float*)d_in[20];
    const float* Wa1   = (const float*)d_in[21];
    const float* ba1   = (const float*)d_in[22];
    const float* Wa2   = (const float*)d_in[23];
    const float* ba2   = (const float*)d_in[24];
    const float* Wc1   = (const float*)d_in[25];
    const float* bc1   = (const float*)d_in[26];
    const float* gc    = (const float*)d_in[27];
    const float* bec   = (const float*)d_in[28];
    const float* Wc2   = (const float*)d_in[29];
    const float* bc2   = (const float*)d_in[30];
    float* out = (float*)d_out;

    float *y1, *y2, *y3, *xpf, *xpb, *gru, *pooled;
    float *sums1, *sums2, *sums3, *sc1, *sh1, *sc2, *sh2, *sc3, *sh3;
    cudaGetSymbolAddress((void**)&y1, g_y1);
    cudaGetSymbolAddress((void**)&y2, g_y2);
    cudaGetSymbolAddress((void**)&y3, g_y3);
    cudaGetSymbolAddress((void**)&xpf, g_xpf);
    cudaGetSymbolAddress((void**)&xpb, g_xpb);
    cudaGetSymbolAddress((void**)&gru, g_gru);
    cudaGetSymbolAddress((void**)&pooled, g_pooled);
    cudaGetSymbolAddress((void**)&sums1, g_sums1);
    cudaGetSymbolAddress((void**)&sums2, g_sums2);
    cudaGetSymbolAddress((void**)&sums3, g_sums3);
    cudaGetSymbolAddress((void**)&sc1, g_sc1);
    cudaGetSymbolAddress((void**)&sh1, g_sh1);
    cudaGetSymbolAddress((void**)&sc2, g_sc2);
    cudaGetSymbolAddress((void**)&sh2, g_sh2);
    cudaGetSymbolAddress((void**)&sc3, g_sc3);
    cudaGetSymbolAddress((void**)&sh3, g_sh3);

    const float invM = 1.f / (float)MROWS;
    const int gx = MROWS / 128;

    zero_stats_kernel<<<1, 512>>>(sums1, sums2, sums3);

    // L1: y1 = x @ W1^T + b1     (N=256, K=80) + fused column stats
    bgemm_kernel<0,1,0><<<dim3(gx, 2), 256>>>(x, W1, b1, nullptr, nullptr,
                                              y1, sums1, MROWS, 256, FF);
    finalize_bn_kernel<<<1, 256>>>(sums1, g1, be1, sc1, sh1, 256, invM);

    // L2: y2 = relu(bn1(y1)) @ W2^T + b2   (N=128, K=256)
    bgemm_kernel<1,1,0><<<dim3(gx, 1), 256>>>(y1, W2, b2, sc1, sh1,
                                              y2, sums2, MROWS, 128, 256);
    finalize_bn_kernel<<<1, 128>>>(sums2, g2, be2, sc2, sh2, 128, invM);

    // L3: y3 = relu(bn2(y2)) @ W3^T + b3   (N=64, K=128)  — NARROW layout
    bgemm_kernel<1,1,1><<<dim3(gx, 1), 256>>>(y2, W3, b3, sc2, sh2,
                                              y3, sums3, MROWS, 64, 128);
    finalize_bn_kernel<<<1, 64>>>(sums3, g3, be3, sc3, sh3, 64, invM);

    // GRU input projections: xp = relu(bn3(y3)) @ Wih^T + bih   (N=96, K=64)
    bgemm_kernel<1,0,0><<<dim3(gx, 1), 256>>>(y3, Wih_f, bih_f, sc3, sh3,
                                              xpf, nullptr, MROWS, 96, 64);
    bgemm_kernel<1,0,0><<<dim3(gx, 1), 256>>>(y3, Wih_b, bih_b, sc3, sh3,
                                              xpb, nullptr, MROWS, 96, 64);

    // GRU recurrence
    gru_kernel<<<dim3(BB, 2), 32>>>(xpf, xpb, Whh_f, bhh_f, Whh_b, bhh_b, gru);

    // attention pooling
    attn_kernel<<<BB, 256>>>(gru, Wa1, ba1, Wa2, ba2, pooled);

    // classifier
    cls_kernel<<<1, 128>>>(pooled, Wc1, bc1, gc, bec, Wc2, bc2, out);
}